// round 6
// baseline (speedup 1.0000x reference)
#include <cuda_runtime.h>
#include <cuda_bf16.h>
#include <cstdint>

#define B_   8
#define NQ_  64
#define N_   257
#define D_   768
#define H_   6
#define R_   64
#define DH_  128
#define MID_ 4096
#define BN_ROWS 2056
#define BQ_ROWS 512
#define K3  (3 * D_)          // 2304: split-bf16 K dimension
#define NKT (K3 / 64)         // 36 k-tiles of 64

// ---------------- scratch (device globals; no allocation allowed) ----------
__device__ __align__(256) __nv_bfloat16 g_x2  [BQ_ROWS * (size_t)K3];
__device__ __align__(256) __nv_bfloat16 g_ctx2[BN_ROWS * (size_t)K3];
__device__ __align__(256) __nv_bfloat16 g_Wq2 [D_   * (size_t)K3];
__device__ __align__(256) __nv_bfloat16 g_Wk2 [D_   * (size_t)K3];
__device__ __align__(256) __nv_bfloat16 g_Wv12[MID_ * (size_t)K3];
__device__ __align__(256) __nv_bfloat16 g_Wout2[D_  * (size_t)K3];
__device__ __align__(256) __nv_bfloat16 g_op2 [BQ_ROWS * (size_t)K3];
__device__ float g_q[BQ_ROWS * (size_t)D_];
__device__ float g_k[BN_ROWS * (size_t)D_];
__device__ float g_mid[BN_ROWS * (size_t)MID_];
__device__ float g_w[(size_t)B_ * H_ * NQ_ * R_];
__device__ float g_outpre[BQ_ROWS * (size_t)D_];

// ---------------------------- PTX helpers ----------------------------------
__device__ __forceinline__ unsigned smem_u32(const void* p) {
    return (unsigned)__cvta_generic_to_shared(p);
}
#define CPA16(dst_u32, src_ptr) \
    asm volatile("cp.async.cg.shared.global [%0], [%1], 16;\n" :: "r"(dst_u32), "l"(src_ptr))
#define LDSM_X4(r0, r1, r2, r3, addr) \
    asm volatile("ldmatrix.sync.aligned.m8n8.x4.shared.b16 {%0,%1,%2,%3}, [%4];" \
                 : "=r"(r0), "=r"(r1), "=r"(r2), "=r"(r3) : "r"(addr))
#define MMA16816(acc, a, b0, b1) \
    asm volatile( \
        "mma.sync.aligned.m16n8k16.row.col.f32.bf16.bf16.f32 " \
        "{%0,%1,%2,%3}, {%4,%5,%6,%7}, {%8,%9}, {%0,%1,%2,%3};\n" \
        : "+f"((acc)[0]), "+f"((acc)[1]), "+f"((acc)[2]), "+f"((acc)[3]) \
        : "r"((a)[0]), "r"((a)[1]), "r"((a)[2]), "r"((a)[3]), "r"(b0), "r"(b1))

__device__ __forceinline__ uint32_t sw128(uint32_t off) {
    return off ^ ((off >> 3) & 0x70);
}

// ---------------------------------------------------------------------------
// Split fp32 -> bf16 hi/lo, block-concatenated along K.
// MODE 0 (A-side): [hi | hi | lo]   MODE 1 (B-side): [hi | lo | hi]
// => A2 @ B2^T = Ahi·Bhi + Ahi·Blo + Alo·Bhi  (drops lo·lo, ~2^-18)
// ---------------------------------------------------------------------------
__device__ __forceinline__ void split_store(const float x, __nv_bfloat16* Y,
                                            size_t base, int mode) {
    const __nv_bfloat16 hi = __float2bfloat16(x);
    const __nv_bfloat16 lo = __float2bfloat16(x - __bfloat162float(hi));
    if (mode == 0) { Y[base] = hi; Y[base + D_] = hi; Y[base + 2 * D_] = lo; }
    else           { Y[base] = hi; Y[base + D_] = lo; Y[base + 2 * D_] = hi; }
}

template <int MODE>
__global__ void split_kernel(const float* __restrict__ X,
                             __nv_bfloat16* __restrict__ Y, int M) {
    const int i = blockIdx.x * 256 + threadIdx.x;
    if (i >= M * D_) return;
    const int row = i / D_, col = i - row * D_;
    split_store(X[i], Y, (size_t)row * K3 + col, MODE);
}

// Three 768x768 weight splits (MODE 1) in one launch; blockIdx.y selects tensor.
__global__ void split3_kernel(const float* __restrict__ X0, __nv_bfloat16* __restrict__ Y0,
                              const float* __restrict__ X1, __nv_bfloat16* __restrict__ Y1,
                              const float* __restrict__ X2, __nv_bfloat16* __restrict__ Y2) {
    const int i = blockIdx.x * 256 + threadIdx.x;
    if (i >= D_ * D_) return;
    const float* X = (blockIdx.y == 0) ? X0 : (blockIdx.y == 1) ? X1 : X2;
    __nv_bfloat16* Y = (blockIdx.y == 0) ? Y0 : (blockIdx.y == 1) ? Y1 : Y2;
    const int row = i / D_, col = i - row * D_;
    split_store(X[i], Y, (size_t)row * K3 + col, 1);
}

// ---------------------------------------------------------------------------
// GEMM 128x128 tile: C[M,N] = A[M,K3] @ B[N,K3]^T. mma.sync + ldmatrix,
// BK=64, 3-stage cp.async, 256 thr = 8 warps (4M x 2N), warp tile 32x64.
// ---------------------------------------------------------------------------
#define STG_BYTES 32768            // (128 + 128) rows * 128 B

__global__ __launch_bounds__(256, 2)
void gemm_mma(const __nv_bfloat16* __restrict__ A,
              const __nv_bfloat16* __restrict__ Bm,
              float* __restrict__ C, int M, int Ncols) {
    extern __shared__ char dyn[];
    const uint32_t base = smem_u32(dyn);

    const int tid = threadIdx.x;
    const int warp = tid >> 5, lane = tid & 31;
    const int wm = warp & 3, wn = warp >> 2;
    const int gr = lane >> 2, tig = lane & 3;
    const int m0 = blockIdx.y * 128, n0 = blockIdx.x * 128;

    const int a_r = (lane & 7) + ((lane >> 3) & 1) * 8;
    const int a_k = (lane >> 4) * 8;
    const int b_c = (lane & 7) + ((lane >> 4) & 1) * 8;
    const int b_k = ((lane >> 3) & 1) * 8;

    float acc[2][8][4];
#pragma unroll
    for (int mi = 0; mi < 2; mi++)
#pragma unroll
        for (int ni = 0; ni < 8; ni++)
#pragma unroll
            for (int j = 0; j < 4; j++) acc[mi][ni][j] = 0.f;

    auto load_stage = [&](int kt) {
        const uint32_t sb = base + (kt % 3) * STG_BYTES;
        const int k0 = kt * 64;
#pragma unroll
        for (int i = 0; i < 4; i++) {
            const int c = tid + i * 256;
            const int row = c >> 3, c16 = c & 7;
            int grow = m0 + row; if (grow >= M) grow = M - 1;
            CPA16(sb + sw128((uint32_t)(row * 128 + c16 * 16)),
                  A + (size_t)grow * K3 + k0 + c16 * 8);
        }
#pragma unroll
        for (int i = 0; i < 4; i++) {
            const int c = tid + i * 256;
            const int row = c >> 3, c16 = c & 7;
            CPA16(sb + 16384 + sw128((uint32_t)(row * 128 + c16 * 16)),
                  Bm + (size_t)(n0 + row) * K3 + k0 + c16 * 8);
        }
        asm volatile("cp.async.commit_group;\n" ::);
    };

    load_stage(0);
    load_stage(1);

    for (int kt = 0; kt < NKT; kt++) {
        const int s = kt % 3;
        asm volatile("cp.async.wait_group 1;\n" ::);
        __syncthreads();
        if (kt + 2 < NKT) load_stage(kt + 2);
        else asm volatile("cp.async.commit_group;\n" ::);

        const uint32_t sA = base + s * STG_BYTES;
        const uint32_t sB = sA + 16384;
#pragma unroll
        for (int kk = 0; kk < 4; kk++) {
            const int k16 = kk * 16;
            uint32_t a[2][4], b[4][4];
#pragma unroll
            for (int mi = 0; mi < 2; mi++) {
                const int r = wm * 32 + mi * 16 + a_r;
                LDSM_X4(a[mi][0], a[mi][1], a[mi][2], a[mi][3],
                        sA + sw128((uint32_t)(r * 128 + (k16 + a_k) * 2)));
            }
#pragma unroll
            for (int nj = 0; nj < 4; nj++) {
                const int cth = wn * 64 + nj * 16 + b_c;
                LDSM_X4(b[nj][0], b[nj][1], b[nj][2], b[nj][3],
                        sB + sw128((uint32_t)(cth * 128 + (k16 + b_k) * 2)));
            }
#pragma unroll
            for (int mi = 0; mi < 2; mi++)
#pragma unroll
                for (int ni = 0; ni < 8; ni++)
                    MMA16816(acc[mi][ni], a[mi],
                             b[ni >> 1][(ni & 1) * 2], b[ni >> 1][(ni & 1) * 2 + 1]);
        }
    }

#pragma unroll
    for (int mi = 0; mi < 2; mi++)
#pragma unroll
        for (int ni = 0; ni < 8; ni++) {
            const int c = n0 + wn * 64 + ni * 8 + 2 * tig;
            int r = m0 + wm * 32 + mi * 16 + gr;
            if (r < M) *(float2*)&C[(size_t)r * Ncols + c] =
                make_float2(acc[mi][ni][0], acc[mi][ni][1]);
            r += 8;
            if (r < M) *(float2*)&C[(size_t)r * Ncols + c] =
                make_float2(acc[mi][ni][2], acc[mi][ni][3]);
        }
}

// ---------------------------------------------------------------------------
// GEMM 64x64 tile for small GEMMs (q, k, out): 128 thr = 4 warps (2M x 2N),
// warp tile 32x32, BK=64, 3-stage. 4x CTA count of the 128-tile variant.
// ---------------------------------------------------------------------------
#define STG64_BYTES 16384          // (64 + 64) rows * 128 B

__global__ __launch_bounds__(128, 3)
void gemm_mma64(const __nv_bfloat16* __restrict__ A,
                const __nv_bfloat16* __restrict__ Bm,
                float* __restrict__ C, int M, int Ncols) {
    extern __shared__ char dyn[];
    const uint32_t base = smem_u32(dyn);

    const int tid = threadIdx.x;
    const int warp = tid >> 5, lane = tid & 31;
    const int wm = warp & 1, wn = warp >> 1;
    const int gr = lane >> 2, tig = lane & 3;
    const int m0 = blockIdx.y * 64, n0 = blockIdx.x * 64;

    const int a_r = (lane & 7) + ((lane >> 3) & 1) * 8;
    const int a_k = (lane >> 4) * 8;
    const int b_c = (lane & 7) + ((lane >> 4) & 1) * 8;
    const int b_k = ((lane >> 3) & 1) * 8;

    float acc[2][4][4];
#pragma unroll
    for (int mi = 0; mi < 2; mi++)
#pragma unroll
        for (int ni = 0; ni < 4; ni++)
#pragma unroll
            for (int j = 0; j < 4; j++) acc[mi][ni][j] = 0.f;

    auto load_stage = [&](int kt) {
        const uint32_t sb = base + (kt % 3) * STG64_BYTES;
        const int k0 = kt * 64;
#pragma unroll
        for (int i = 0; i < 4; i++) {                 // A: 64 rows x 128B
            const int c = tid + i * 128;
            const int row = c >> 3, c16 = c & 7;
            int grow = m0 + row; if (grow >= M) grow = M - 1;
            CPA16(sb + sw128((uint32_t)(row * 128 + c16 * 16)),
                  A + (size_t)grow * K3 + k0 + c16 * 8);
        }
#pragma unroll
        for (int i = 0; i < 4; i++) {                 // B: 64 rows x 128B
            const int c = tid + i * 128;
            const int row = c >> 3, c16 = c & 7;
            CPA16(sb + 8192 + sw128((uint32_t)(row * 128 + c16 * 16)),
                  Bm + (size_t)(n0 + row) * K3 + k0 + c16 * 8);
        }
        asm volatile("cp.async.commit_group;\n" ::);
    };

    load_stage(0);
    load_stage(1);

    for (int kt = 0; kt < NKT; kt++) {
        const int s = kt % 3;
        asm volatile("cp.async.wait_group 1;\n" ::);
        __syncthreads();
        if (kt + 2 < NKT) load_stage(kt + 2);
        else asm volatile("cp.async.commit_group;\n" ::);

        const uint32_t sA = base + s * STG64_BYTES;
        const uint32_t sB = sA + 8192;
#pragma unroll
        for (int kk = 0; kk < 4; kk++) {
            const int k16 = kk * 16;
            uint32_t a[2][4], b[2][4];
#pragma unroll
            for (int mi = 0; mi < 2; mi++) {
                const int r = wm * 32 + mi * 16 + a_r;
                LDSM_X4(a[mi][0], a[mi][1], a[mi][2], a[mi][3],
                        sA + sw128((uint32_t)(r * 128 + (k16 + a_k) * 2)));
            }
#pragma unroll
            for (int nj = 0; nj < 2; nj++) {
                const int cth = wn * 32 + nj * 16 + b_c;
                LDSM_X4(b[nj][0], b[nj][1], b[nj][2], b[nj][3],
                        sB + sw128((uint32_t)(cth * 128 + (k16 + b_k) * 2)));
            }
#pragma unroll
            for (int mi = 0; mi < 2; mi++)
#pragma unroll
                for (int ni = 0; ni < 4; ni++)
                    MMA16816(acc[mi][ni], a[mi],
                             b[ni >> 1][(ni & 1) * 2], b[ni >> 1][(ni & 1) * 2 + 1]);
        }
    }

#pragma unroll
    for (int mi = 0; mi < 2; mi++)
#pragma unroll
        for (int ni = 0; ni < 4; ni++) {
            const int c = n0 + wn * 32 + ni * 8 + 2 * tig;
            int r = m0 + wm * 32 + mi * 16 + gr;
            if (r < M) *(float2*)&C[(size_t)r * Ncols + c] =
                make_float2(acc[mi][ni][0], acc[mi][ni][1]);
            r += 8;
            if (r < M) *(float2*)&C[(size_t)r * Ncols + c] =
                make_float2(acc[mi][ni][2], acc[mi][ni][3]);
        }
}

// ---------------------------------------------------------------------------
// Row LayerNorm over MID_=4096, in place. One block (256 thr) per row.
// ---------------------------------------------------------------------------
__global__ void ln_kernel(float* __restrict__ mid,
                          const float* __restrict__ g,
                          const float* __restrict__ bt) {
    const int row = blockIdx.x;
    float* p = mid + (size_t)row * MID_;
    const int tid = threadIdx.x;
    const int lane = tid & 31, warp = tid >> 5;

    float vals[16];
    float s = 0.f, ss = 0.f;
#pragma unroll
    for (int j = 0; j < 16; j++) {
        const float x = p[tid + (j << 8)];
        vals[j] = x; s += x; ss += x * x;
    }
#pragma unroll
    for (int off = 16; off; off >>= 1) {
        s  += __shfl_xor_sync(~0u, s,  off);
        ss += __shfl_xor_sync(~0u, ss, off);
    }
    __shared__ float rs[8], rss[8];
    if (lane == 0) { rs[warp] = s; rss[warp] = ss; }
    __syncthreads();
    s = 0.f; ss = 0.f;
#pragma unroll
    for (int k = 0; k < 8; k++) { s += rs[k]; ss += rss[k]; }
    const float mu  = s * (1.f / MID_);
    const float var = ss * (1.f / MID_) - mu * mu;
    const float inv = rsqrtf(var + 1e-5f);
#pragma unroll
    for (int j = 0; j < 16; j++) {
        const int idx = tid + (j << 8);
        p[idx] = (vals[j] - mu) * inv * g[idx] + bt[idx];
    }
}

// ---------------------------------------------------------------------------
// Attention + rank-space contraction (fp32-exact).
// ---------------------------------------------------------------------------
__global__ void attn_w_kernel(const float* __restrict__ qb,
                              const float* __restrict__ kb,
                              const float* __restrict__ mid,
                              float* __restrict__ w) {
    const int i = blockIdx.x;
    const int h = blockIdx.y;
    const int b = blockIdx.z;
    const int tid = threadIdx.x;
    const int lane = tid & 31, warp = tid >> 5;

    __shared__ float qs[DH_];
    __shared__ float sim[N_];
    __shared__ float red8[8];
    __shared__ float wred[4][R_];
    __shared__ float s_total;

    if (tid < DH_) qs[tid] = qb[((size_t)(b * NQ_ + i)) * D_ + h * DH_ + tid];
    __syncthreads();

    for (int n = warp; n < N_; n += 8) {
        const float* kp = kb + ((size_t)(b * N_ + n)) * D_ + h * DH_;
        float acc = 0.f;
#pragma unroll
        for (int d = lane; d < DH_; d += 32) acc += qs[d] * kp[d];
#pragma unroll
        for (int off = 16; off; off >>= 1) acc += __shfl_xor_sync(~0u, acc, off);
        if (lane == 0) sim[n] = acc * 0.0883883476483184406f;
    }
    __syncthreads();

    float m = -1e30f;
    for (int n = tid; n < N_; n += 256) m = fmaxf(m, sim[n]);
#pragma unroll
    for (int off = 16; off; off >>= 1) m = fmaxf(m, __shfl_xor_sync(~0u, m, off));
    if (lane == 0) red8[warp] = m;
    __syncthreads();
    float mm = red8[0];
#pragma unroll
    for (int k = 1; k < 8; k++) mm = fmaxf(mm, red8[k]);
    __syncthreads();

    float s = 0.f;
    for (int n = tid; n < N_; n += 256) {
        const float e = __expf(sim[n] - mm);
        sim[n] = e;
        s += e;
    }
#pragma unroll
    for (int off = 16; off; off >>= 1) s += __shfl_xor_sync(~0u, s, off);
    if (lane == 0) red8[warp] = s;
    __syncthreads();
    if (tid == 0) {
        float t = 0.f;
#pragma unroll
        for (int k = 0; k < 8; k++) t += red8[k];
        s_total = 1.f / t;
    }
    __syncthreads();

    const int r = tid & 63, grp = tid >> 6;
    float acc = 0.f;
    for (int n = grp; n < N_; n += 4)
        acc += sim[n] * mid[((size_t)(b * N_ + n)) * MID_ + i * R_ + r];
    wred[grp][r] = acc;
    __syncthreads();
    if (grp == 0) {
        const float v = (wred[0][r] + wred[1][r] + wred[2][r] + wred[3][r]) * s_total;
        w[(((size_t)b * H_ + h) * NQ_ + i) * R_ + r] = v;
    }
}

// ---------------------------------------------------------------------------
// Rank expansion: outpre[b,i,d] = sum_r Wconv[i,d,r] * w[b, d/128, i, r]
// ---------------------------------------------------------------------------
__global__ void convout_kernel(const float* __restrict__ w,
                               const float* __restrict__ Wconv,
                               float* __restrict__ outpre) {
    const int i = blockIdx.x % NQ_;
    const int b = blockIdx.x / NQ_;
    const int tid = threadIdx.x;

    __shared__ float ws[H_ * R_];
    for (int j = tid; j < H_ * R_; j += 256)
        ws[j] = w[(((size_t)b * H_ + (j >> 6)) * NQ_ + i) * R_ + (j & 63)];
    __syncthreads();

    for (int d = tid; d < D_; d += 256) {
        const float* wc = Wconv + ((size_t)i * D_ + d) * R_;
        const float* wv = &ws[(d >> 7) * R_];
        float acc = 0.f;
#pragma unroll
        for (int r = 0; r < R_; r += 4) {
            const float4 c4 = *(const float4*)&wc[r];
            acc += c4.x * wv[r] + c4.y * wv[r + 1] + c4.z * wv[r + 2] + c4.w * wv[r + 3];
        }
        outpre[((size_t)b * NQ_ + i) * D_ + d] = acc;
    }
}

// ---------------------------------------------------------------------------
extern "C" void kernel_launch(void* const* d_in, const int* in_sizes, int n_in,
                              void* d_out, int out_size) {
    const float* x     = (const float*)d_in[0];
    const float* ctx   = (const float*)d_in[1];
    const float* Wq    = (const float*)d_in[2];
    const float* Wk    = (const float*)d_in[3];
    const float* Wv1   = (const float*)d_in[4];
    const float* ln_g  = (const float*)d_in[5];
    const float* ln_b  = (const float*)d_in[6];
    const float* Wconv = (const float*)d_in[7];
    const float* Wout  = (const float*)d_in[8];
    float* out = (float*)d_out;

    __nv_bfloat16 *x2, *ctx2, *Wq2, *Wk2, *Wv12, *Wout2, *op2;
    float *qp, *kp, *midp, *wp, *opp;
    cudaGetSymbolAddress((void**)&x2,   g_x2);
    cudaGetSymbolAddress((void**)&ctx2, g_ctx2);
    cudaGetSymbolAddress((void**)&Wq2,  g_Wq2);
    cudaGetSymbolAddress((void**)&Wk2,  g_Wk2);
    cudaGetSymbolAddress((void**)&Wv12, g_Wv12);
    cudaGetSymbolAddress((void**)&Wout2,g_Wout2);
    cudaGetSymbolAddress((void**)&op2,  g_op2);
    cudaGetSymbolAddress((void**)&qp,   g_q);
    cudaGetSymbolAddress((void**)&kp,   g_k);
    cudaGetSymbolAddress((void**)&midp, g_mid);
    cudaGetSymbolAddress((void**)&wp,   g_w);
    cudaGetSymbolAddress((void**)&opp,  g_outpre);

    const int SMEM   = 3 * STG_BYTES;     // 98304
    const int SMEM64 = 3 * STG64_BYTES;   // 49152
    cudaFuncSetAttribute(gemm_mma,   cudaFuncAttributeMaxDynamicSharedMemorySize, SMEM);
    cudaFuncSetAttribute(gemm_mma64, cudaFuncAttributeMaxDynamicSharedMemorySize, SMEM64);

    const int T = 256;
    auto blks = [](int n) { return (n + 255) / 256; };

    // split conversions
    split_kernel<0><<<blks(BQ_ROWS * D_), T>>>(x,    x2,   BQ_ROWS);
    split_kernel<0><<<blks(BN_ROWS * D_), T>>>(ctx,  ctx2, BN_ROWS);
    split3_kernel<<<dim3(blks(D_ * D_), 3), T>>>(Wq, Wq2, Wk, Wk2, Wout, Wout2);
    split_kernel<1><<<blks(MID_ * D_),    T>>>(Wv1,  Wv12, MID_);

    // q = x @ Wq^T          (512 x 768): 64-tiles -> 96 CTAs
    gemm_mma64<<<dim3(D_ / 64, BQ_ROWS / 64), 128, SMEM64>>>(x2, Wq2, qp, BQ_ROWS, D_);
    // k = ctx @ Wk^T        (2056 x 768): 64-tiles -> 12 x 33 = 396 CTAs
    gemm_mma64<<<dim3(D_ / 64, (BN_ROWS + 63) / 64), 128, SMEM64>>>(ctx2, Wk2, kp, BN_ROWS, D_);
    // mid = ctx @ Wv1^T     (2056 x 4096): 128-tiles (L2-traffic optimal)
    gemm_mma<<<dim3(MID_ / 128, (BN_ROWS + 127) / 128), T, SMEM>>>(ctx2, Wv12, midp, BN_ROWS, MID_);

    ln_kernel<<<BN_ROWS, 256>>>(midp, ln_g, ln_b);
    attn_w_kernel<<<dim3(NQ_, H_, B_), 256>>>(qp, kp, midp, wp);
    convout_kernel<<<BQ_ROWS, 256>>>(wp, Wconv, opp);

    // final = outpre @ Wout^T  (512 x 768): 64-tiles
    split_kernel<0><<<blks(BQ_ROWS * D_), T>>>(opp, op2, BQ_ROWS);
    gemm_mma64<<<dim3(D_ / 64, BQ_ROWS / 64), 128, SMEM64>>>(op2, Wout2, out, BQ_ROWS, D_);
}

// round 7
// speedup vs baseline: 1.4011x; 1.4011x over previous
#include <cuda_runtime.h>
#include <cuda_bf16.h>
#include <cstdint>

#define B_   8
#define NQ_  64
#define N_   257
#define D_   768
#define H_   6
#define R_   64
#define DH_  128
#define MID_ 4096
#define BN_ROWS 2056
#define BQ_ROWS 512
#define K3  (3 * D_)          // 2304: split-bf16 K dimension
#define NKT (K3 / 64)         // 36 k-tiles of 64

// ---------------- scratch (device globals; no allocation allowed) ----------
__device__ __align__(256) __nv_bfloat16 g_x2  [BQ_ROWS * (size_t)K3];
__device__ __align__(256) __nv_bfloat16 g_ctx2[BN_ROWS * (size_t)K3];
__device__ __align__(256) __nv_bfloat16 g_Wq2 [D_   * (size_t)K3];
__device__ __align__(256) __nv_bfloat16 g_Wk2 [D_   * (size_t)K3];
__device__ __align__(256) __nv_bfloat16 g_Wv12[MID_ * (size_t)K3];
__device__ __align__(256) __nv_bfloat16 g_Wout2[D_  * (size_t)K3];
__device__ __align__(256) __nv_bfloat16 g_op2 [BQ_ROWS * (size_t)K3];
__device__ float g_q[BQ_ROWS * (size_t)D_];
__device__ float g_k[BN_ROWS * (size_t)D_];
__device__ float g_mid[BN_ROWS * (size_t)MID_];
__device__ float g_w[(size_t)B_ * H_ * NQ_ * R_];
__device__ float g_outpre[BQ_ROWS * (size_t)D_];
__device__ float g_part[2 * BN_ROWS * (size_t)D_];   // split-K partials (reused)

// ---------------------------- PTX helpers ----------------------------------
__device__ __forceinline__ unsigned smem_u32(const void* p) {
    return (unsigned)__cvta_generic_to_shared(p);
}
#define CPA16(dst_u32, src_ptr) \
    asm volatile("cp.async.cg.shared.global [%0], [%1], 16;\n" :: "r"(dst_u32), "l"(src_ptr))
#define LDSM_X4(r0, r1, r2, r3, addr) \
    asm volatile("ldmatrix.sync.aligned.m8n8.x4.shared.b16 {%0,%1,%2,%3}, [%4];" \
                 : "=r"(r0), "=r"(r1), "=r"(r2), "=r"(r3) : "r"(addr))
#define MMA16816(acc, a, b0, b1) \
    asm volatile( \
        "mma.sync.aligned.m16n8k16.row.col.f32.bf16.bf16.f32 " \
        "{%0,%1,%2,%3}, {%4,%5,%6,%7}, {%8,%9}, {%0,%1,%2,%3};\n" \
        : "+f"((acc)[0]), "+f"((acc)[1]), "+f"((acc)[2]), "+f"((acc)[3]) \
        : "r"((a)[0]), "r"((a)[1]), "r"((a)[2]), "r"((a)[3]), "r"(b0), "r"(b1))

__device__ __forceinline__ uint32_t sw128(uint32_t off) {
    return off ^ ((off >> 3) & 0x70);
}

// ---------------------------------------------------------------------------
// Split fp32 -> bf16 hi/lo, block-concatenated along K.
// MODE 0 (A-side): [hi | hi | lo]   MODE 1 (B-side): [hi | lo | hi]
// ---------------------------------------------------------------------------
__device__ __forceinline__ void split_store(const float x, __nv_bfloat16* Y,
                                            size_t base, int mode) {
    const __nv_bfloat16 hi = __float2bfloat16(x);
    const __nv_bfloat16 lo = __float2bfloat16(x - __bfloat162float(hi));
    if (mode == 0) { Y[base] = hi; Y[base + D_] = hi; Y[base + 2 * D_] = lo; }
    else           { Y[base] = hi; Y[base + D_] = lo; Y[base + 2 * D_] = hi; }
}

template <int MODE>
__global__ void split_kernel(const float* __restrict__ X,
                             __nv_bfloat16* __restrict__ Y, int M) {
    const int i = blockIdx.x * 256 + threadIdx.x;
    if (i >= M * D_) return;
    const int row = i / D_, col = i - row * D_;
    split_store(X[i], Y, (size_t)row * K3 + col, MODE);
}

__global__ void split3_kernel(const float* __restrict__ X0, __nv_bfloat16* __restrict__ Y0,
                              const float* __restrict__ X1, __nv_bfloat16* __restrict__ Y1,
                              const float* __restrict__ X2, __nv_bfloat16* __restrict__ Y2) {
    const int i = blockIdx.x * 256 + threadIdx.x;
    if (i >= D_ * D_) return;
    const float* X = (blockIdx.y == 0) ? X0 : (blockIdx.y == 1) ? X1 : X2;
    __nv_bfloat16* Y = (blockIdx.y == 0) ? Y0 : (blockIdx.y == 1) ? Y1 : Y2;
    const int row = i / D_, col = i - row * D_;
    split_store(X[i], Y, (size_t)row * K3 + col, 1);
}

// ---------------------------------------------------------------------------
// GEMM 128x128 tile: C[M,N] = A[M,K3] @ B[N,K3]^T. mma.sync + ldmatrix,
// BK=64, 3-stage cp.async, 256 thr = 8 warps (4M x 2N), warp tile 32x64.
// Split-K: blockIdx.z handles k-tiles [z*nkt, (z+1)*nkt), writes C + z*M*N.
// ---------------------------------------------------------------------------
#define STG_BYTES 32768            // (128 + 128) rows * 128 B

__global__ __launch_bounds__(256, 2)
void gemm_mma(const __nv_bfloat16* __restrict__ A,
              const __nv_bfloat16* __restrict__ Bm,
              float* __restrict__ C, int M, int Ncols, int nkt) {
    extern __shared__ char dyn[];
    const uint32_t base = smem_u32(dyn);

    const int tid = threadIdx.x;
    const int warp = tid >> 5, lane = tid & 31;
    const int wm = warp & 3, wn = warp >> 2;
    const int gr = lane >> 2, tig = lane & 3;
    const int m0 = blockIdx.y * 128, n0 = blockIdx.x * 128;
    const int kt0 = blockIdx.z * nkt;
    float* Cz = C + (size_t)blockIdx.z * M * Ncols;

    const int a_r = (lane & 7) + ((lane >> 3) & 1) * 8;
    const int a_k = (lane >> 4) * 8;
    const int b_c = (lane & 7) + ((lane >> 4) & 1) * 8;
    const int b_k = ((lane >> 3) & 1) * 8;

    float acc[2][8][4];
#pragma unroll
    for (int mi = 0; mi < 2; mi++)
#pragma unroll
        for (int ni = 0; ni < 8; ni++)
#pragma unroll
            for (int j = 0; j < 4; j++) acc[mi][ni][j] = 0.f;

    auto load_stage = [&](int kt) {
        const uint32_t sb = base + (kt % 3) * STG_BYTES;
        const int k0 = (kt0 + kt) * 64;
#pragma unroll
        for (int i = 0; i < 4; i++) {
            const int c = tid + i * 256;
            const int row = c >> 3, c16 = c & 7;
            int grow = m0 + row; if (grow >= M) grow = M - 1;
            CPA16(sb + sw128((uint32_t)(row * 128 + c16 * 16)),
                  A + (size_t)grow * K3 + k0 + c16 * 8);
        }
#pragma unroll
        for (int i = 0; i < 4; i++) {
            const int c = tid + i * 256;
            const int row = c >> 3, c16 = c & 7;
            CPA16(sb + 16384 + sw128((uint32_t)(row * 128 + c16 * 16)),
                  Bm + (size_t)(n0 + row) * K3 + k0 + c16 * 8);
        }
        asm volatile("cp.async.commit_group;\n" ::);
    };

    load_stage(0);
    load_stage(1);

    for (int kt = 0; kt < nkt; kt++) {
        const int s = kt % 3;
        asm volatile("cp.async.wait_group 1;\n" ::);
        __syncthreads();
        if (kt + 2 < nkt) load_stage(kt + 2);
        else asm volatile("cp.async.commit_group;\n" ::);

        const uint32_t sA = base + s * STG_BYTES;
        const uint32_t sB = sA + 16384;
#pragma unroll
        for (int kk = 0; kk < 4; kk++) {
            const int k16 = kk * 16;
            uint32_t a[2][4], b[4][4];
#pragma unroll
            for (int mi = 0; mi < 2; mi++) {
                const int r = wm * 32 + mi * 16 + a_r;
                LDSM_X4(a[mi][0], a[mi][1], a[mi][2], a[mi][3],
                        sA + sw128((uint32_t)(r * 128 + (k16 + a_k) * 2)));
            }
#pragma unroll
            for (int nj = 0; nj < 4; nj++) {
                const int cth = wn * 64 + nj * 16 + b_c;
                LDSM_X4(b[nj][0], b[nj][1], b[nj][2], b[nj][3],
                        sB + sw128((uint32_t)(cth * 128 + (k16 + b_k) * 2)));
            }
#pragma unroll
            for (int mi = 0; mi < 2; mi++)
#pragma unroll
                for (int ni = 0; ni < 8; ni++)
                    MMA16816(acc[mi][ni], a[mi],
                             b[ni >> 1][(ni & 1) * 2], b[ni >> 1][(ni & 1) * 2 + 1]);
        }
    }

#pragma unroll
    for (int mi = 0; mi < 2; mi++)
#pragma unroll
        for (int ni = 0; ni < 8; ni++) {
            const int c = n0 + wn * 64 + ni * 8 + 2 * tig;
            int r = m0 + wm * 32 + mi * 16 + gr;
            if (r < M) *(float2*)&Cz[(size_t)r * Ncols + c] =
                make_float2(acc[mi][ni][0], acc[mi][ni][1]);
            r += 8;
            if (r < M) *(float2*)&Cz[(size_t)r * Ncols + c] =
                make_float2(acc[mi][ni][2], acc[mi][ni][3]);
        }
}

// ---------------------------------------------------------------------------
// Split-K reduction: C[i] = sum_{z<KSPL} P[z*elems + i]. float4 vectorized.
// ---------------------------------------------------------------------------
template <int KSPL>
__global__ void reduce_k(const float* __restrict__ P, float* __restrict__ C,
                         int elems4) {
    const int i = blockIdx.x * 256 + threadIdx.x;
    if (i >= elems4) return;
    const float4* p = (const float4*)P;
    float4 v = p[i];
#pragma unroll
    for (int z = 1; z < KSPL; z++) {
        const float4 u = p[(size_t)z * elems4 + i];
        v.x += u.x; v.y += u.y; v.z += u.z; v.w += u.w;
    }
    ((float4*)C)[i] = v;
}

// ---------------------------------------------------------------------------
// Row LayerNorm over MID_=4096, in place. One block (256 thr) per row.
// ---------------------------------------------------------------------------
__global__ void ln_kernel(float* __restrict__ mid,
                          const float* __restrict__ g,
                          const float* __restrict__ bt) {
    const int row = blockIdx.x;
    float* p = mid + (size_t)row * MID_;
    const int tid = threadIdx.x;
    const int lane = tid & 31, warp = tid >> 5;

    float vals[16];
    float s = 0.f, ss = 0.f;
#pragma unroll
    for (int j = 0; j < 16; j++) {
        const float x = p[tid + (j << 8)];
        vals[j] = x; s += x; ss += x * x;
    }
#pragma unroll
    for (int off = 16; off; off >>= 1) {
        s  += __shfl_xor_sync(~0u, s,  off);
        ss += __shfl_xor_sync(~0u, ss, off);
    }
    __shared__ float rs[8], rss[8];
    if (lane == 0) { rs[warp] = s; rss[warp] = ss; }
    __syncthreads();
    s = 0.f; ss = 0.f;
#pragma unroll
    for (int k = 0; k < 8; k++) { s += rs[k]; ss += rss[k]; }
    const float mu  = s * (1.f / MID_);
    const float var = ss * (1.f / MID_) - mu * mu;
    const float inv = rsqrtf(var + 1e-5f);
#pragma unroll
    for (int j = 0; j < 16; j++) {
        const int idx = tid + (j << 8);
        p[idx] = (vals[j] - mu) * inv * g[idx] + bt[idx];
    }
}

// ---------------------------------------------------------------------------
// Attention + rank-space contraction (fp32-exact).
// ---------------------------------------------------------------------------
__global__ void attn_w_kernel(const float* __restrict__ qb,
                              const float* __restrict__ kb,
                              const float* __restrict__ mid,
                              float* __restrict__ w) {
    const int i = blockIdx.x;
    const int h = blockIdx.y;
    const int b = blockIdx.z;
    const int tid = threadIdx.x;
    const int lane = tid & 31, warp = tid >> 5;

    __shared__ float qs[DH_];
    __shared__ float sim[N_];
    __shared__ float red8[8];
    __shared__ float wred[4][R_];
    __shared__ float s_total;

    if (tid < DH_) qs[tid] = qb[((size_t)(b * NQ_ + i)) * D_ + h * DH_ + tid];
    __syncthreads();

    for (int n = warp; n < N_; n += 8) {
        const float* kp = kb + ((size_t)(b * N_ + n)) * D_ + h * DH_;
        float acc = 0.f;
#pragma unroll
        for (int d = lane; d < DH_; d += 32) acc += qs[d] * kp[d];
#pragma unroll
        for (int off = 16; off; off >>= 1) acc += __shfl_xor_sync(~0u, acc, off);
        if (lane == 0) sim[n] = acc * 0.0883883476483184406f;
    }
    __syncthreads();

    float m = -1e30f;
    for (int n = tid; n < N_; n += 256) m = fmaxf(m, sim[n]);
#pragma unroll
    for (int off = 16; off; off >>= 1) m = fmaxf(m, __shfl_xor_sync(~0u, m, off));
    if (lane == 0) red8[warp] = m;
    __syncthreads();
    float mm = red8[0];
#pragma unroll
    for (int k = 1; k < 8; k++) mm = fmaxf(mm, red8[k]);
    __syncthreads();

    float s = 0.f;
    for (int n = tid; n < N_; n += 256) {
        const float e = __expf(sim[n] - mm);
        sim[n] = e;
        s += e;
    }
#pragma unroll
    for (int off = 16; off; off >>= 1) s += __shfl_xor_sync(~0u, s, off);
    if (lane == 0) red8[warp] = s;
    __syncthreads();
    if (tid == 0) {
        float t = 0.f;
#pragma unroll
        for (int k = 0; k < 8; k++) t += red8[k];
        s_total = 1.f / t;
    }
    __syncthreads();

    const int r = tid & 63, grp = tid >> 6;
    float acc = 0.f;
    for (int n = grp; n < N_; n += 4)
        acc += sim[n] * mid[((size_t)(b * N_ + n)) * MID_ + i * R_ + r];
    wred[grp][r] = acc;
    __syncthreads();
    if (grp == 0) {
        const float v = (wred[0][r] + wred[1][r] + wred[2][r] + wred[3][r]) * s_total;
        w[(((size_t)b * H_ + h) * NQ_ + i) * R_ + r] = v;
    }
}

// ---------------------------------------------------------------------------
// Rank expansion: outpre[b,i,d] = sum_r Wconv[i,d,r] * w[b, d/128, i, r]
// ---------------------------------------------------------------------------
__global__ void convout_kernel(const float* __restrict__ w,
                               const float* __restrict__ Wconv,
                               float* __restrict__ outpre) {
    const int i = blockIdx.x % NQ_;
    const int b = blockIdx.x / NQ_;
    const int tid = threadIdx.x;

    __shared__ float ws[H_ * R_];
    for (int j = tid; j < H_ * R_; j += 256)
        ws[j] = w[(((size_t)b * H_ + (j >> 6)) * NQ_ + i) * R_ + (j & 63)];
    __syncthreads();

    for (int d = tid; d < D_; d += 256) {
        const float* wc = Wconv + ((size_t)i * D_ + d) * R_;
        const float* wv = &ws[(d >> 7) * R_];
        float acc = 0.f;
#pragma unroll
        for (int r = 0; r < R_; r += 4) {
            const float4 c4 = *(const float4*)&wc[r];
            acc += c4.x * wv[r] + c4.y * wv[r + 1] + c4.z * wv[r + 2] + c4.w * wv[r + 3];
        }
        outpre[((size_t)b * NQ_ + i) * D_ + d] = acc;
    }
}

// ---------------------------------------------------------------------------
extern "C" void kernel_launch(void* const* d_in, const int* in_sizes, int n_in,
                              void* d_out, int out_size) {
    const float* x     = (const float*)d_in[0];
    const float* ctx   = (const float*)d_in[1];
    const float* Wq    = (const float*)d_in[2];
    const float* Wk    = (const float*)d_in[3];
    const float* Wv1   = (const float*)d_in[4];
    const float* ln_g  = (const float*)d_in[5];
    const float* ln_b  = (const float*)d_in[6];
    const float* Wconv = (const float*)d_in[7];
    const float* Wout  = (const float*)d_in[8];
    float* out = (float*)d_out;

    __nv_bfloat16 *x2, *ctx2, *Wq2, *Wk2, *Wv12, *Wout2, *op2;
    float *qp, *kp, *midp, *wp, *opp, *pp;
    cudaGetSymbolAddress((void**)&x2,   g_x2);
    cudaGetSymbolAddress((void**)&ctx2, g_ctx2);
    cudaGetSymbolAddress((void**)&Wq2,  g_Wq2);
    cudaGetSymbolAddress((void**)&Wk2,  g_Wk2);
    cudaGetSymbolAddress((void**)&Wv12, g_Wv12);
    cudaGetSymbolAddress((void**)&Wout2,g_Wout2);
    cudaGetSymbolAddress((void**)&op2,  g_op2);
    cudaGetSymbolAddress((void**)&qp,   g_q);
    cudaGetSymbolAddress((void**)&kp,   g_k);
    cudaGetSymbolAddress((void**)&midp, g_mid);
    cudaGetSymbolAddress((void**)&wp,   g_w);
    cudaGetSymbolAddress((void**)&opp,  g_outpre);
    cudaGetSymbolAddress((void**)&pp,   g_part);

    const int SMEM = 3 * STG_BYTES;   // 98304
    cudaFuncSetAttribute(gemm_mma, cudaFuncAttributeMaxDynamicSharedMemorySize, SMEM);

    const int T = 256;
    auto blks = [](int n) { return (n + 255) / 256; };

    // split conversions
    split_kernel<0><<<blks(BQ_ROWS * D_), T>>>(x,    x2,   BQ_ROWS);
    split_kernel<0><<<blks(BN_ROWS * D_), T>>>(ctx,  ctx2, BN_ROWS);
    split3_kernel<<<dim3(blks(D_ * D_), 3), T>>>(Wq, Wq2, Wk, Wk2, Wout, Wout2);
    split_kernel<1><<<blks(MID_ * D_),    T>>>(Wv1,  Wv12, MID_);

    // q = x @ Wq^T (512 x 768): split-K=4 -> 96 CTAs x 9 iters, then reduce
    gemm_mma<<<dim3(D_ / 128, BQ_ROWS / 128, 4), T, SMEM>>>(
        x2, Wq2, pp, BQ_ROWS, D_, NKT / 4);
    reduce_k<4><<<blks(BQ_ROWS * D_ / 4), T>>>(pp, qp, BQ_ROWS * D_ / 4);

    // k = ctx @ Wk^T (2056 x 768): split-K=2 -> 204 CTAs x 18 iters
    gemm_mma<<<dim3(D_ / 128, (BN_ROWS + 127) / 128, 2), T, SMEM>>>(
        ctx2, Wk2, pp, BN_ROWS, D_, NKT / 2);
    reduce_k<2><<<blks(BN_ROWS * D_ / 4), T>>>(pp, kp, BN_ROWS * D_ / 4);

    // mid = ctx @ Wv1^T (2056 x 4096): no split (throughput-limited)
    gemm_mma<<<dim3(MID_ / 128, (BN_ROWS + 127) / 128, 1), T, SMEM>>>(
        ctx2, Wv12, midp, BN_ROWS, MID_, NKT);

    ln_kernel<<<BN_ROWS, 256>>>(midp, ln_g, ln_b);
    attn_w_kernel<<<dim3(NQ_, H_, B_), 256>>>(qp, kp, midp, wp);
    convout_kernel<<<BQ_ROWS, 256>>>(wp, Wconv, opp);

    // final = outpre @ Wout^T (512 x 768): split-K=4
    split_kernel<0><<<blks(BQ_ROWS * D_), T>>>(opp, op2, BQ_ROWS);
    gemm_mma<<<dim3(D_ / 128, BQ_ROWS / 128, 4), T, SMEM>>>(
        op2, Wout2, pp, BQ_ROWS, D_, NKT / 4);
    reduce_k<4><<<blks(BQ_ROWS * D_ / 4), T>>>(pp, out, BQ_ROWS * D_ / 4);
}

// round 8
// speedup vs baseline: 1.6441x; 1.1734x over previous
#include <cuda_runtime.h>
#include <cuda_bf16.h>
#include <cstdint>

#define B_   8
#define NQ_  64
#define N_   257
#define D_   768
#define H_   6
#define R_   64
#define DH_  128
#define MID_ 4096
#define BN_ROWS 2056
#define BQ_ROWS 512
#define K3  (3 * D_)          // 2304: split-bf16 K dimension
#define NKT (K3 / 64)         // 36 k-tiles of 64

// fused-GEMM job boundaries
#define MID_TILES 544          // 17 m-tiles x 32 n-tiles
#define KQ_B0     544          // k: 2 z x 17 x 6 = 204
#define Q_B0      748          // q: 4 z x 4 x 6  = 96
#define TOT_TILES 844

// ---------------- scratch (device globals; no allocation allowed) ----------
__device__ __align__(256) __nv_bfloat16 g_x2  [BQ_ROWS * (size_t)K3];
__device__ __align__(256) __nv_bfloat16 g_ctx2[BN_ROWS * (size_t)K3];
__device__ __align__(256) __nv_bfloat16 g_Wq2 [D_   * (size_t)K3];
__device__ __align__(256) __nv_bfloat16 g_Wk2 [D_   * (size_t)K3];
__device__ __align__(256) __nv_bfloat16 g_Wv12[MID_ * (size_t)K3];
__device__ __align__(256) __nv_bfloat16 g_Wout2[D_  * (size_t)K3];
__device__ __align__(256) __nv_bfloat16 g_op2 [BQ_ROWS * (size_t)K3];
__device__ float g_q[BQ_ROWS * (size_t)D_];
__device__ float g_k[BN_ROWS * (size_t)D_];
__device__ float g_mid[BN_ROWS * (size_t)MID_];
__device__ float g_w[(size_t)B_ * H_ * NQ_ * R_];
__device__ float g_outpre[BQ_ROWS * (size_t)D_];
// k partials (2 x 2056 x 768) then q partials (4 x 512 x 768)
__device__ float g_part[2 * BN_ROWS * (size_t)D_ + 4 * BQ_ROWS * (size_t)D_];

// ---------------------------- PTX helpers ----------------------------------
__device__ __forceinline__ unsigned smem_u32(const void* p) {
    return (unsigned)__cvta_generic_to_shared(p);
}
#define CPA16(dst_u32, src_ptr) \
    asm volatile("cp.async.cg.shared.global [%0], [%1], 16;\n" :: "r"(dst_u32), "l"(src_ptr))
#define LDSM_X4(r0, r1, r2, r3, addr) \
    asm volatile("ldmatrix.sync.aligned.m8n8.x4.shared.b16 {%0,%1,%2,%3}, [%4];" \
                 : "=r"(r0), "=r"(r1), "=r"(r2), "=r"(r3) : "r"(addr))
#define MMA16816(acc, a, b0, b1) \
    asm volatile( \
        "mma.sync.aligned.m16n8k16.row.col.f32.bf16.bf16.f32 " \
        "{%0,%1,%2,%3}, {%4,%5,%6,%7}, {%8,%9}, {%0,%1,%2,%3};\n" \
        : "+f"((acc)[0]), "+f"((acc)[1]), "+f"((acc)[2]), "+f"((acc)[3]) \
        : "r"((a)[0]), "r"((a)[1]), "r"((a)[2]), "r"((a)[3]), "r"(b0), "r"(b1))

__device__ __forceinline__ uint32_t sw128(uint32_t off) {
    return off ^ ((off >> 3) & 0x70);
}

// ---------------------------------------------------------------------------
// Split fp32 -> bf16 hi/lo, float4-vectorized (4 cols/thread).
// MODE 0 (A-side): [hi | hi | lo]   MODE 1 (B-side): [hi | lo | hi]
// ---------------------------------------------------------------------------
__device__ __forceinline__ void split_store4(float4 v, __nv_bfloat16* Y, size_t base,
                                             int mode) {
    __nv_bfloat16 h[4], l[4];
    const float xs[4] = {v.x, v.y, v.z, v.w};
#pragma unroll
    for (int j = 0; j < 4; j++) {
        h[j] = __float2bfloat16(xs[j]);
        l[j] = __float2bfloat16(xs[j] - __bfloat162float(h[j]));
    }
    __nv_bfloat162* y0 = (__nv_bfloat162*)(Y + base);
    __nv_bfloat162* y1 = (__nv_bfloat162*)(Y + base + D_);
    __nv_bfloat162* y2 = (__nv_bfloat162*)(Y + base + 2 * D_);
    const __nv_bfloat162 hp0 = {h[0], h[1]}, hp1 = {h[2], h[3]};
    const __nv_bfloat162 lp0 = {l[0], l[1]}, lp1 = {l[2], l[3]};
    y0[0] = hp0; y0[1] = hp1;
    if (mode == 0) { y1[0] = hp0; y1[1] = hp1; y2[0] = lp0; y2[1] = lp1; }
    else           { y1[0] = lp0; y1[1] = lp1; y2[0] = hp0; y2[1] = hp1; }
}

template <int MODE>
__global__ void split_kernel(const float* __restrict__ X,
                             __nv_bfloat16* __restrict__ Y, int M) {
    const int i = blockIdx.x * 256 + threadIdx.x;
    if (i >= M * (D_ / 4)) return;
    const int row = i / (D_ / 4), c4 = i - row * (D_ / 4);
    split_store4(((const float4*)X)[i], Y, (size_t)row * K3 + c4 * 4, MODE);
}

__global__ void split3_kernel(const float* __restrict__ X0, __nv_bfloat16* __restrict__ Y0,
                              const float* __restrict__ X1, __nv_bfloat16* __restrict__ Y1,
                              const float* __restrict__ X2, __nv_bfloat16* __restrict__ Y2) {
    const int i = blockIdx.x * 256 + threadIdx.x;
    if (i >= D_ * (D_ / 4)) return;
    const float* X = (blockIdx.y == 0) ? X0 : (blockIdx.y == 1) ? X1 : X2;
    __nv_bfloat16* Y = (blockIdx.y == 0) ? Y0 : (blockIdx.y == 1) ? Y1 : Y2;
    const int row = i / (D_ / 4), c4 = i - row * (D_ / 4);
    split_store4(((const float4*)X)[i], Y, (size_t)row * K3 + c4 * 4, 1);
}

// ---------------------------------------------------------------------------
// GEMM body, 128x128 tile: C[M,N] = A[M,K3] @ B[N,K3]^T. mma.sync + ldmatrix,
// BK=64, 3-stage cp.async, 256 thr = 8 warps (4M x 2N), warp tile 32x64.
// ---------------------------------------------------------------------------
#define STG_BYTES 32768            // (128 + 128) rows * 128 B

__device__ __forceinline__
void gemm_body(const __nv_bfloat16* __restrict__ A,
               const __nv_bfloat16* __restrict__ Bm,
               float* __restrict__ C, int M, int Ncols,
               int nkt, int kt0, int mt, int nt, char* dyn) {
    const uint32_t base = smem_u32(dyn);

    const int tid = threadIdx.x;
    const int warp = tid >> 5, lane = tid & 31;
    const int wm = warp & 3, wn = warp >> 2;
    const int gr = lane >> 2, tig = lane & 3;
    const int m0 = mt * 128, n0 = nt * 128;

    const int a_r = (lane & 7) + ((lane >> 3) & 1) * 8;
    const int a_k = (lane >> 4) * 8;
    const int b_c = (lane & 7) + ((lane >> 4) & 1) * 8;
    const int b_k = ((lane >> 3) & 1) * 8;

    float acc[2][8][4];
#pragma unroll
    for (int mi = 0; mi < 2; mi++)
#pragma unroll
        for (int ni = 0; ni < 8; ni++)
#pragma unroll
            for (int j = 0; j < 4; j++) acc[mi][ni][j] = 0.f;

    auto load_stage = [&](int kt) {
        const uint32_t sb = base + (kt % 3) * STG_BYTES;
        const int k0 = (kt0 + kt) * 64;
#pragma unroll
        for (int i = 0; i < 4; i++) {
            const int c = tid + i * 256;
            const int row = c >> 3, c16 = c & 7;
            int grow = m0 + row; if (grow >= M) grow = M - 1;
            CPA16(sb + sw128((uint32_t)(row * 128 + c16 * 16)),
                  A + (size_t)grow * K3 + k0 + c16 * 8);
        }
#pragma unroll
        for (int i = 0; i < 4; i++) {
            const int c = tid + i * 256;
            const int row = c >> 3, c16 = c & 7;
            CPA16(sb + 16384 + sw128((uint32_t)(row * 128 + c16 * 16)),
                  Bm + (size_t)(n0 + row) * K3 + k0 + c16 * 8);
        }
        asm volatile("cp.async.commit_group;\n" ::);
    };

    load_stage(0);
    load_stage(1);

    for (int kt = 0; kt < nkt; kt++) {
        const int s = kt % 3;
        asm volatile("cp.async.wait_group 1;\n" ::);
        __syncthreads();
        if (kt + 2 < nkt) load_stage(kt + 2);
        else asm volatile("cp.async.commit_group;\n" ::);

        const uint32_t sA = base + s * STG_BYTES;
        const uint32_t sB = sA + 16384;
#pragma unroll
        for (int kk = 0; kk < 4; kk++) {
            const int k16 = kk * 16;
            uint32_t a[2][4], b[4][4];
#pragma unroll
            for (int mi = 0; mi < 2; mi++) {
                const int r = wm * 32 + mi * 16 + a_r;
                LDSM_X4(a[mi][0], a[mi][1], a[mi][2], a[mi][3],
                        sA + sw128((uint32_t)(r * 128 + (k16 + a_k) * 2)));
            }
#pragma unroll
            for (int nj = 0; nj < 4; nj++) {
                const int cth = wn * 64 + nj * 16 + b_c;
                LDSM_X4(b[nj][0], b[nj][1], b[nj][2], b[nj][3],
                        sB + sw128((uint32_t)(cth * 128 + (k16 + b_k) * 2)));
            }
#pragma unroll
            for (int mi = 0; mi < 2; mi++)
#pragma unroll
                for (int ni = 0; ni < 8; ni++)
                    MMA16816(acc[mi][ni], a[mi],
                             b[ni >> 1][(ni & 1) * 2], b[ni >> 1][(ni & 1) * 2 + 1]);
        }
    }

#pragma unroll
    for (int mi = 0; mi < 2; mi++)
#pragma unroll
        for (int ni = 0; ni < 8; ni++) {
            const int c = n0 + wn * 64 + ni * 8 + 2 * tig;
            int r = m0 + wm * 32 + mi * 16 + gr;
            if (r < M) *(float2*)&C[(size_t)r * Ncols + c] =
                make_float2(acc[mi][ni][0], acc[mi][ni][1]);
            r += 8;
            if (r < M) *(float2*)&C[(size_t)r * Ncols + c] =
                make_float2(acc[mi][ni][2], acc[mi][ni][3]);
        }
}

// Fused launch: mid (no split-K) + k (split-K2) + q (split-K4) in one grid.
// mid CTAs first so k/q tiles backfill mid's ragged tail wave.
__global__ __launch_bounds__(256, 2)
void gemm_fused(const __nv_bfloat16* __restrict__ ctx2,
                const __nv_bfloat16* __restrict__ Wv12, float* __restrict__ midp,
                const __nv_bfloat16* __restrict__ Wk2,  float* __restrict__ kpart,
                const __nv_bfloat16* __restrict__ x2,
                const __nv_bfloat16* __restrict__ Wq2,  float* __restrict__ qpart) {
    extern __shared__ char dyn[];
    const int bid = blockIdx.x;
    if (bid < MID_TILES) {
        gemm_body(ctx2, Wv12, midp, BN_ROWS, MID_, NKT, 0,
                  bid / 32, bid % 32, dyn);
    } else if (bid < Q_B0) {
        const int t = bid - KQ_B0;
        const int z = t / 102, r = t - z * 102;       // 17 x 6 tiles
        gemm_body(ctx2, Wk2, kpart + (size_t)z * BN_ROWS * D_, BN_ROWS, D_,
                  NKT / 2, z * (NKT / 2), r / 6, r % 6, dyn);
    } else {
        const int t = bid - Q_B0;
        const int z = t / 24, r = t - z * 24;         // 4 x 6 tiles
        gemm_body(x2, Wq2, qpart + (size_t)z * BQ_ROWS * D_, BQ_ROWS, D_,
                  NKT / 4, z * (NKT / 4), r / 6, r % 6, dyn);
    }
}

// Standalone (used for the out GEMM, split-K via blockIdx.z)
__global__ __launch_bounds__(256, 2)
void gemm_mma(const __nv_bfloat16* __restrict__ A,
              const __nv_bfloat16* __restrict__ Bm,
              float* __restrict__ C, int M, int Ncols, int nkt) {
    extern __shared__ char dyn[];
    gemm_body(A, Bm, C + (size_t)blockIdx.z * M * Ncols, M, Ncols,
              nkt, blockIdx.z * nkt, blockIdx.y, blockIdx.x, dyn);
}

// ---------------------------------------------------------------------------
// Split-K reduction: C[i] = sum_{z<KSPL} P[z*elems + i]. float4 vectorized.
// ---------------------------------------------------------------------------
template <int KSPL>
__global__ void reduce_k(const float* __restrict__ P, float* __restrict__ C,
                         int elems4) {
    const int i = blockIdx.x * 256 + threadIdx.x;
    if (i >= elems4) return;
    const float4* p = (const float4*)P;
    float4 v = p[i];
#pragma unroll
    for (int z = 1; z < KSPL; z++) {
        const float4 u = p[(size_t)z * elems4 + i];
        v.x += u.x; v.y += u.y; v.z += u.z; v.w += u.w;
    }
    ((float4*)C)[i] = v;
}

// ---------------------------------------------------------------------------
// Row LayerNorm over MID_=4096, in place, float4-vectorized.
// ---------------------------------------------------------------------------
__global__ void ln_kernel(float* __restrict__ mid,
                          const float* __restrict__ g,
                          const float* __restrict__ bt) {
    const int row = blockIdx.x;
    float4* p = (float4*)(mid + (size_t)row * MID_);
    const float4* g4 = (const float4*)g;
    const float4* b4 = (const float4*)bt;
    const int tid = threadIdx.x;
    const int lane = tid & 31, warp = tid >> 5;

    float4 v[4];
    float s = 0.f, ss = 0.f;
#pragma unroll
    for (int j = 0; j < 4; j++) {
        v[j] = p[tid + (j << 8)];
        s  += v[j].x + v[j].y + v[j].z + v[j].w;
        ss += v[j].x * v[j].x + v[j].y * v[j].y + v[j].z * v[j].z + v[j].w * v[j].w;
    }
#pragma unroll
    for (int off = 16; off; off >>= 1) {
        s  += __shfl_xor_sync(~0u, s,  off);
        ss += __shfl_xor_sync(~0u, ss, off);
    }
    __shared__ float rs[8], rss[8];
    if (lane == 0) { rs[warp] = s; rss[warp] = ss; }
    __syncthreads();
    s = 0.f; ss = 0.f;
#pragma unroll
    for (int k = 0; k < 8; k++) { s += rs[k]; ss += rss[k]; }
    const float mu  = s * (1.f / MID_);
    const float var = ss * (1.f / MID_) - mu * mu;
    const float inv = rsqrtf(var + 1e-5f);
#pragma unroll
    for (int j = 0; j < 4; j++) {
        const int idx = tid + (j << 8);
        const float4 gv = g4[idx], bv = b4[idx];
        float4 o;
        o.x = (v[j].x - mu) * inv * gv.x + bv.x;
        o.y = (v[j].y - mu) * inv * gv.y + bv.y;
        o.z = (v[j].z - mu) * inv * gv.z + bv.z;
        o.w = (v[j].w - mu) * inv * gv.w + bv.w;
        p[idx] = o;
    }
}

// ---------------------------------------------------------------------------
// Attention + rank-space contraction (fp32-exact).
// ---------------------------------------------------------------------------
__global__ void attn_w_kernel(const float* __restrict__ qb,
                              const float* __restrict__ kb,
                              const float* __restrict__ mid,
                              float* __restrict__ w) {
    const int i = blockIdx.x;
    const int h = blockIdx.y;
    const int b = blockIdx.z;
    const int tid = threadIdx.x;
    const int lane = tid & 31, warp = tid >> 5;

    __shared__ float qs[DH_];
    __shared__ float sim[N_];
    __shared__ float red8[8];
    __shared__ float wred[4][R_];
    __shared__ float s_total;

    if (tid < DH_) qs[tid] = qb[((size_t)(b * NQ_ + i)) * D_ + h * DH_ + tid];
    __syncthreads();

    for (int n = warp; n < N_; n += 8) {
        const float* kp = kb + ((size_t)(b * N_ + n)) * D_ + h * DH_;
        float acc = 0.f;
#pragma unroll
        for (int d = lane; d < DH_; d += 32) acc += qs[d] * kp[d];
#pragma unroll
        for (int off = 16; off; off >>= 1) acc += __shfl_xor_sync(~0u, acc, off);
        if (lane == 0) sim[n] = acc * 0.0883883476483184406f;
    }
    __syncthreads();

    float m = -1e30f;
    for (int n = tid; n < N_; n += 256) m = fmaxf(m, sim[n]);
#pragma unroll
    for (int off = 16; off; off >>= 1) m = fmaxf(m, __shfl_xor_sync(~0u, m, off));
    if (lane == 0) red8[warp] = m;
    __syncthreads();
    float mm = red8[0];
#pragma unroll
    for (int k = 1; k < 8; k++) mm = fmaxf(mm, red8[k]);
    __syncthreads();

    float s = 0.f;
    for (int n = tid; n < N_; n += 256) {
        const float e = __expf(sim[n] - mm);
        sim[n] = e;
        s += e;
    }
#pragma unroll
    for (int off = 16; off; off >>= 1) s += __shfl_xor_sync(~0u, s, off);
    if (lane == 0) red8[warp] = s;
    __syncthreads();
    if (tid == 0) {
        float t = 0.f;
#pragma unroll
        for (int k = 0; k < 8; k++) t += red8[k];
        s_total = 1.f / t;
    }
    __syncthreads();

    const int r = tid & 63, grp = tid >> 6;
    float acc = 0.f;
    for (int n = grp; n < N_; n += 4)
        acc += sim[n] * mid[((size_t)(b * N_ + n)) * MID_ + i * R_ + r];
    wred[grp][r] = acc;
    __syncthreads();
    if (grp == 0) {
        const float v = (wred[0][r] + wred[1][r] + wred[2][r] + wred[3][r]) * s_total;
        w[(((size_t)b * H_ + h) * NQ_ + i) * R_ + r] = v;
    }
}

// ---------------------------------------------------------------------------
// Rank expansion: outpre[b,i,d] = sum_r Wconv[i,d,r] * w[b, d/128, i, r]
// ---------------------------------------------------------------------------
__global__ void convout_kernel(const float* __restrict__ w,
                               const float* __restrict__ Wconv,
                               float* __restrict__ outpre) {
    const int i = blockIdx.x % NQ_;
    const int b = blockIdx.x / NQ_;
    const int tid = threadIdx.x;

    __shared__ float ws[H_ * R_];
    for (int j = tid; j < H_ * R_; j += 256)
        ws[j] = w[(((size_t)b * H_ + (j >> 6)) * NQ_ + i) * R_ + (j & 63)];
    __syncthreads();

    for (int d = tid; d < D_; d += 256) {
        const float* wc = Wconv + ((size_t)i * D_ + d) * R_;
        const float* wv = &ws[(d >> 7) * R_];
        float acc = 0.f;
#pragma unroll
        for (int r = 0; r < R_; r += 4) {
            const float4 c4 = *(const float4*)&wc[r];
            acc += c4.x * wv[r] + c4.y * wv[r + 1] + c4.z * wv[r + 2] + c4.w * wv[r + 3];
        }
        outpre[((size_t)b * NQ_ + i) * D_ + d] = acc;
    }
}

// ---------------------------------------------------------------------------
extern "C" void kernel_launch(void* const* d_in, const int* in_sizes, int n_in,
                              void* d_out, int out_size) {
    const float* x     = (const float*)d_in[0];
    const float* ctx   = (const float*)d_in[1];
    const float* Wq    = (const float*)d_in[2];
    const float* Wk    = (const float*)d_in[3];
    const float* Wv1   = (const float*)d_in[4];
    const float* ln_g  = (const float*)d_in[5];
    const float* ln_b  = (const float*)d_in[6];
    const float* Wconv = (const float*)d_in[7];
    const float* Wout  = (const float*)d_in[8];
    float* out = (float*)d_out;

    __nv_bfloat16 *x2, *ctx2, *Wq2, *Wk2, *Wv12, *Wout2, *op2;
    float *qp, *kp, *midp, *wp, *opp, *pp;
    cudaGetSymbolAddress((void**)&x2,   g_x2);
    cudaGetSymbolAddress((void**)&ctx2, g_ctx2);
    cudaGetSymbolAddress((void**)&Wq2,  g_Wq2);
    cudaGetSymbolAddress((void**)&Wk2,  g_Wk2);
    cudaGetSymbolAddress((void**)&Wv12, g_Wv12);
    cudaGetSymbolAddress((void**)&Wout2,g_Wout2);
    cudaGetSymbolAddress((void**)&op2,  g_op2);
    cudaGetSymbolAddress((void**)&qp,   g_q);
    cudaGetSymbolAddress((void**)&kp,   g_k);
    cudaGetSymbolAddress((void**)&midp, g_mid);
    cudaGetSymbolAddress((void**)&wp,   g_w);
    cudaGetSymbolAddress((void**)&opp,  g_outpre);
    cudaGetSymbolAddress((void**)&pp,   g_part);
    float* kpart = pp;
    float* qpart = pp + 2 * (size_t)BN_ROWS * D_;

    const int SMEM = 3 * STG_BYTES;   // 98304
    cudaFuncSetAttribute(gemm_fused, cudaFuncAttributeMaxDynamicSharedMemorySize, SMEM);
    cudaFuncSetAttribute(gemm_mma,   cudaFuncAttributeMaxDynamicSharedMemorySize, SMEM);

    const int T = 256;
    auto blks = [](int n) { return (n + 255) / 256; };

    // split conversions (float4-vectorized)
    split_kernel<0><<<blks(BQ_ROWS * D_ / 4), T>>>(x,    x2,   BQ_ROWS);
    split_kernel<0><<<blks(BN_ROWS * D_ / 4), T>>>(ctx,  ctx2, BN_ROWS);
    split3_kernel<<<dim3(blks(D_ * D_ / 4), 3), T>>>(Wq, Wq2, Wk, Wk2, Wout, Wout2);
    split_kernel<1><<<blks(MID_ * D_ / 4),    T>>>(Wv1,  Wv12, MID_);

    // ONE launch: mid + k(split2) + q(split4), 844 CTAs
    gemm_fused<<<TOT_TILES, T, SMEM>>>(ctx2, Wv12, midp, Wk2, kpart, x2, Wq2, qpart);
    reduce_k<4><<<blks(BQ_ROWS * D_ / 4), T>>>(qpart, qp, BQ_ROWS * D_ / 4);
    reduce_k<2><<<blks(BN_ROWS * D_ / 4), T>>>(kpart, kp, BN_ROWS * D_ / 4);

    ln_kernel<<<BN_ROWS, 256>>>(midp, ln_g, ln_b);
    attn_w_kernel<<<dim3(NQ_, H_, B_), 256>>>(qp, kp, midp, wp);
    convout_kernel<<<BQ_ROWS, 256>>>(wp, Wconv, opp);

    // final = outpre @ Wout^T (512 x 768): split-K=4
    split_kernel<0><<<blks(BQ_ROWS * D_ / 4), T>>>(opp, op2, BQ_ROWS);
    gemm_mma<<<dim3(D_ / 128, BQ_ROWS / 128, 4), T, SMEM>>>(
        op2, Wout2, pp, BQ_ROWS, D_, NKT / 4);
    reduce_k<4><<<blks(BQ_ROWS * D_ / 4), T>>>(pp, out, BQ_ROWS * D_ / 4);
}

// round 9
// speedup vs baseline: 1.6974x; 1.0324x over previous
#include <cuda_runtime.h>
#include <cuda_bf16.h>
#include <cstdint>

#define B_   8
#define NQ_  64
#define N_   257
#define D_   768
#define H_   6
#define R_   64
#define DH_  128
#define MID_ 4096
#define BN_ROWS 2056
#define BQ_ROWS 512
#define K3  (3 * D_)          // 2304: split-bf16 K (out-GEMM only)
#define NKT (K3 / 64)         // 36 bf16 k-tiles
#define NKT32 (D_ / 32)       // 24 tf32 k-tiles

// fused-GEMM job boundaries (tf32 path)
#define MID_TILES 544          // 17 m-tiles x 32 n-tiles, 24 iters
#define KQ_B0     544          // k: 2 z x 17 x 6 = 204, 12 iters
#define Q_B0      748          // q: 4 z x 4 x 6  = 96,  6 iters
#define TOT_TILES 844

// ---------------- scratch (device globals; no allocation allowed) ----------
__device__ __align__(256) __nv_bfloat16 g_Wout2[D_  * (size_t)K3];
__device__ __align__(256) __nv_bfloat16 g_op2 [BQ_ROWS * (size_t)K3];
__device__ float g_q[BQ_ROWS * (size_t)D_];
__device__ float g_k[BN_ROWS * (size_t)D_];
__device__ float g_mid[BN_ROWS * (size_t)MID_];
__device__ float g_w[(size_t)B_ * H_ * NQ_ * R_];
__device__ float g_outpre[BQ_ROWS * (size_t)D_];
// k partials (2 x 2056 x 768) then q partials (4 x 512 x 768)
__device__ float g_part[2 * BN_ROWS * (size_t)D_ + 4 * BQ_ROWS * (size_t)D_];

// ---------------------------- PTX helpers ----------------------------------
__device__ __forceinline__ unsigned smem_u32(const void* p) {
    return (unsigned)__cvta_generic_to_shared(p);
}
#define CPA16(dst_u32, src_ptr) \
    asm volatile("cp.async.cg.shared.global [%0], [%1], 16;\n" :: "r"(dst_u32), "l"(src_ptr))
#define LDSM_X4(r0, r1, r2, r3, addr) \
    asm volatile("ldmatrix.sync.aligned.m8n8.x4.shared.b16 {%0,%1,%2,%3}, [%4];" \
                 : "=r"(r0), "=r"(r1), "=r"(r2), "=r"(r3) : "r"(addr))
#define MMA16816(acc, a, b0, b1) \
    asm volatile( \
        "mma.sync.aligned.m16n8k16.row.col.f32.bf16.bf16.f32 " \
        "{%0,%1,%2,%3}, {%4,%5,%6,%7}, {%8,%9}, {%0,%1,%2,%3};\n" \
        : "+f"((acc)[0]), "+f"((acc)[1]), "+f"((acc)[2]), "+f"((acc)[3]) \
        : "r"((a)[0]), "r"((a)[1]), "r"((a)[2]), "r"((a)[3]), "r"(b0), "r"(b1))
#define MMA1688_TF32(acc, a, b) \
    asm volatile( \
        "mma.sync.aligned.m16n8k8.row.col.f32.tf32.tf32.f32 " \
        "{%0,%1,%2,%3}, {%4,%5,%6,%7}, {%8,%9}, {%0,%1,%2,%3};\n" \
        : "+f"((acc)[0]), "+f"((acc)[1]), "+f"((acc)[2]), "+f"((acc)[3]) \
        : "r"((a)[0]), "r"((a)[1]), "r"((a)[2]), "r"((a)[3]), \
          "r"((b)[0]), "r"((b)[1]))

__device__ __forceinline__ uint32_t sw128(uint32_t off) {
    return off ^ ((off >> 3) & 0x70);
}
// LDS fp32 from swizzled smem + round-to-nearest tf32 (RNA — unbiased!)
__device__ __forceinline__ uint32_t lds_tf32(uint32_t addr) {
    float v;
    asm volatile("ld.shared.f32 %0, [%1];" : "=f"(v) : "r"(addr));
    uint32_t t;
    asm volatile("cvt.rna.tf32.f32 %0, %1;" : "=r"(t) : "f"(v));
    return t;
}

// ---------------------------------------------------------------------------
// Split fp32 -> bf16 hi/lo (out-GEMM path only).
// MODE 0 (A-side): [hi | hi | lo]   MODE 1 (B-side): [hi | lo | hi]
// ---------------------------------------------------------------------------
__device__ __forceinline__ void split_store4(float4 v, __nv_bfloat16* Y, size_t base,
                                             int mode) {
    __nv_bfloat16 h[4], l[4];
    const float xs[4] = {v.x, v.y, v.z, v.w};
#pragma unroll
    for (int j = 0; j < 4; j++) {
        h[j] = __float2bfloat16(xs[j]);
        l[j] = __float2bfloat16(xs[j] - __bfloat162float(h[j]));
    }
    __nv_bfloat162* y0 = (__nv_bfloat162*)(Y + base);
    __nv_bfloat162* y1 = (__nv_bfloat162*)(Y + base + D_);
    __nv_bfloat162* y2 = (__nv_bfloat162*)(Y + base + 2 * D_);
    const __nv_bfloat162 hp0 = {h[0], h[1]}, hp1 = {h[2], h[3]};
    const __nv_bfloat162 lp0 = {l[0], l[1]}, lp1 = {l[2], l[3]};
    y0[0] = hp0; y0[1] = hp1;
    if (mode == 0) { y1[0] = hp0; y1[1] = hp1; y2[0] = lp0; y2[1] = lp1; }
    else           { y1[0] = lp0; y1[1] = lp1; y2[0] = hp0; y2[1] = hp1; }
}

template <int MODE>
__global__ void split_kernel(const float* __restrict__ X,
                             __nv_bfloat16* __restrict__ Y, int M) {
    const int i = blockIdx.x * 256 + threadIdx.x;
    if (i >= M * (D_ / 4)) return;
    const int row = i / (D_ / 4), c4 = i - row * (D_ / 4);
    split_store4(((const float4*)X)[i], Y, (size_t)row * K3 + c4 * 4, MODE);
}

// ---------------------------------------------------------------------------
// TF32 GEMM body, 128x128 tile: C = A[M,768] @ B[N,768]^T, fp32 in/out.
// BK=32 fp32 (128B rows), 3-stage cp.async, 256 thr = 8 warps (4M x 2N).
// ---------------------------------------------------------------------------
#define STG_BYTES 32768            // (128 + 128) rows * 128 B

__device__ __forceinline__
void gemm_body_tf32(const float* __restrict__ A,
                    const float* __restrict__ Bm,
                    float* __restrict__ C, int M, int Ncols,
                    int nkt, int kt0, int mt, int nt, char* dyn) {
    const uint32_t base = smem_u32(dyn);

    const int tid = threadIdx.x;
    const int warp = tid >> 5, lane = tid & 31;
    const int wm = warp & 3, wn = warp >> 2;
    const int gr = lane >> 2, tig = lane & 3;
    const int m0 = mt * 128, n0 = nt * 128;

    float acc[2][8][4];
#pragma unroll
    for (int mi = 0; mi < 2; mi++)
#pragma unroll
        for (int ni = 0; ni < 8; ni++)
#pragma unroll
            for (int j = 0; j < 4; j++) acc[mi][ni][j] = 0.f;

    auto load_stage = [&](int kt) {
        const uint32_t sb = base + (kt % 3) * STG_BYTES;
        const int k0 = (kt0 + kt) * 32;           // fp32 col offset
#pragma unroll
        for (int i = 0; i < 4; i++) {             // A: 128 rows x 128B
            const int c = tid + i * 256;
            const int row = c >> 3, c16 = c & 7;
            int grow = m0 + row; if (grow >= M) grow = M - 1;
            CPA16(sb + sw128((uint32_t)(row * 128 + c16 * 16)),
                  A + (size_t)grow * D_ + k0 + c16 * 4);
        }
#pragma unroll
        for (int i = 0; i < 4; i++) {             // B: 128 rows x 128B
            const int c = tid + i * 256;
            const int row = c >> 3, c16 = c & 7;
            CPA16(sb + 16384 + sw128((uint32_t)(row * 128 + c16 * 16)),
                  Bm + (size_t)(n0 + row) * D_ + k0 + c16 * 4);
        }
        asm volatile("cp.async.commit_group;\n" ::);
    };

    load_stage(0);
    load_stage(1);

    for (int kt = 0; kt < nkt; kt++) {
        const int s = kt % 3;
        asm volatile("cp.async.wait_group 1;\n" ::);
        __syncthreads();
        if (kt + 2 < nkt) load_stage(kt + 2);
        else asm volatile("cp.async.commit_group;\n" ::);

        const uint32_t sA = base + s * STG_BYTES;
        const uint32_t sB = sA + 16384;
#pragma unroll
        for (int kk = 0; kk < 4; kk++) {
            const int kc = kk * 8;                // fp32 k-base within tile
            uint32_t a[2][4], b[8][2];
#pragma unroll
            for (int mi = 0; mi < 2; mi++) {
                const int r = wm * 32 + mi * 16 + gr;
                a[mi][0] = lds_tf32(sA + sw128((uint32_t)(r * 128 + (kc + tig) * 4)));
                a[mi][1] = lds_tf32(sA + sw128((uint32_t)((r + 8) * 128 + (kc + tig) * 4)));
                a[mi][2] = lds_tf32(sA + sw128((uint32_t)(r * 128 + (kc + tig + 4) * 4)));
                a[mi][3] = lds_tf32(sA + sw128((uint32_t)((r + 8) * 128 + (kc + tig + 4) * 4)));
            }
#pragma unroll
            for (int nj = 0; nj < 8; nj++) {
                const int cn = wn * 64 + nj * 8 + gr;
                b[nj][0] = lds_tf32(sB + sw128((uint32_t)(cn * 128 + (kc + tig) * 4)));
                b[nj][1] = lds_tf32(sB + sw128((uint32_t)(cn * 128 + (kc + tig + 4) * 4)));
            }
#pragma unroll
            for (int mi = 0; mi < 2; mi++)
#pragma unroll
                for (int ni = 0; ni < 8; ni++)
                    MMA1688_TF32(acc[mi][ni], a[mi], b[ni]);
        }
    }

#pragma unroll
    for (int mi = 0; mi < 2; mi++)
#pragma unroll
        for (int ni = 0; ni < 8; ni++) {
            const int c = n0 + wn * 64 + ni * 8 + 2 * tig;
            int r = m0 + wm * 32 + mi * 16 + gr;
            if (r < M) *(float2*)&C[(size_t)r * Ncols + c] =
                make_float2(acc[mi][ni][0], acc[mi][ni][1]);
            r += 8;
            if (r < M) *(float2*)&C[(size_t)r * Ncols + c] =
                make_float2(acc[mi][ni][2], acc[mi][ni][3]);
        }
}

// Fused tf32 launch: mid + k (split-K2) + q (split-K4), one grid, fp32 inputs.
__global__ __launch_bounds__(256, 2)
void gemm_fused_tf32(const float* __restrict__ ctx,
                     const float* __restrict__ Wv1, float* __restrict__ midp,
                     const float* __restrict__ Wk,  float* __restrict__ kpart,
                     const float* __restrict__ x,
                     const float* __restrict__ Wq,  float* __restrict__ qpart) {
    extern __shared__ char dyn[];
    const int bid = blockIdx.x;
    if (bid < MID_TILES) {
        gemm_body_tf32(ctx, Wv1, midp, BN_ROWS, MID_, NKT32, 0,
                       bid / 32, bid % 32, dyn);
    } else if (bid < Q_B0) {
        const int t = bid - KQ_B0;
        const int z = t / 102, r = t - z * 102;       // 17 x 6 tiles
        gemm_body_tf32(ctx, Wk, kpart + (size_t)z * BN_ROWS * D_, BN_ROWS, D_,
                       NKT32 / 2, z * (NKT32 / 2), r / 6, r % 6, dyn);
    } else {
        const int t = bid - Q_B0;
        const int z = t / 24, r = t - z * 24;         // 4 x 6 tiles
        gemm_body_tf32(x, Wq, qpart + (size_t)z * BQ_ROWS * D_, BQ_ROWS, D_,
                       NKT32 / 4, z * (NKT32 / 4), r / 6, r % 6, dyn);
    }
}

// ---------------------------------------------------------------------------
// bf16 split GEMM body (out-GEMM only): C = A[M,K3] @ B[N,K3]^T.
// ---------------------------------------------------------------------------
__device__ __forceinline__
void gemm_body(const __nv_bfloat16* __restrict__ A,
               const __nv_bfloat16* __restrict__ Bm,
               float* __restrict__ C, int M, int Ncols,
               int nkt, int kt0, int mt, int nt, char* dyn) {
    const uint32_t base = smem_u32(dyn);

    const int tid = threadIdx.x;
    const int warp = tid >> 5, lane = tid & 31;
    const int wm = warp & 3, wn = warp >> 2;
    const int gr = lane >> 2, tig = lane & 3;
    const int m0 = mt * 128, n0 = nt * 128;

    const int a_r = (lane & 7) + ((lane >> 3) & 1) * 8;
    const int a_k = (lane >> 4) * 8;
    const int b_c = (lane & 7) + ((lane >> 4) & 1) * 8;
    const int b_k = ((lane >> 3) & 1) * 8;

    float acc[2][8][4];
#pragma unroll
    for (int mi = 0; mi < 2; mi++)
#pragma unroll
        for (int ni = 0; ni < 8; ni++)
#pragma unroll
            for (int j = 0; j < 4; j++) acc[mi][ni][j] = 0.f;

    auto load_stage = [&](int kt) {
        const uint32_t sb = base + (kt % 3) * STG_BYTES;
        const int k0 = (kt0 + kt) * 64;
#pragma unroll
        for (int i = 0; i < 4; i++) {
            const int c = tid + i * 256;
            const int row = c >> 3, c16 = c & 7;
            int grow = m0 + row; if (grow >= M) grow = M - 1;
            CPA16(sb + sw128((uint32_t)(row * 128 + c16 * 16)),
                  A + (size_t)grow * K3 + k0 + c16 * 8);
        }
#pragma unroll
        for (int i = 0; i < 4; i++) {
            const int c = tid + i * 256;
            const int row = c >> 3, c16 = c & 7;
            CPA16(sb + 16384 + sw128((uint32_t)(row * 128 + c16 * 16)),
                  Bm + (size_t)(n0 + row) * K3 + k0 + c16 * 8);
        }
        asm volatile("cp.async.commit_group;\n" ::);
    };

    load_stage(0);
    load_stage(1);

    for (int kt = 0; kt < nkt; kt++) {
        const int s = kt % 3;
        asm volatile("cp.async.wait_group 1;\n" ::);
        __syncthreads();
        if (kt + 2 < nkt) load_stage(kt + 2);
        else asm volatile("cp.async.commit_group;\n" ::);

        const uint32_t sA = base + s * STG_BYTES;
        const uint32_t sB = sA + 16384;
#pragma unroll
        for (int kk = 0; kk < 4; kk++) {
            const int k16 = kk * 16;
            uint32_t a[2][4], b[4][4];
#pragma unroll
            for (int mi = 0; mi < 2; mi++) {
                const int r = wm * 32 + mi * 16 + a_r;
                LDSM_X4(a[mi][0], a[mi][1], a[mi][2], a[mi][3],
                        sA + sw128((uint32_t)(r * 128 + (k16 + a_k) * 2)));
            }
#pragma unroll
            for (int nj = 0; nj < 4; nj++) {
                const int cth = wn * 64 + nj * 16 + b_c;
                LDSM_X4(b[nj][0], b[nj][1], b[nj][2], b[nj][3],
                        sB + sw128((uint32_t)(cth * 128 + (k16 + b_k) * 2)));
            }
#pragma unroll
            for (int mi = 0; mi < 2; mi++)
#pragma unroll
                for (int ni = 0; ni < 8; ni++)
                    MMA16816(acc[mi][ni], a[mi],
                             b[ni >> 1][(ni & 1) * 2], b[ni >> 1][(ni & 1) * 2 + 1]);
        }
    }

#pragma unroll
    for (int mi = 0; mi < 2; mi++)
#pragma unroll
        for (int ni = 0; ni < 8; ni++) {
            const int c = n0 + wn * 64 + ni * 8 + 2 * tig;
            int r = m0 + wm * 32 + mi * 16 + gr;
            if (r < M) *(float2*)&C[(size_t)r * Ncols + c] =
                make_float2(acc[mi][ni][0], acc[mi][ni][1]);
            r += 8;
            if (r < M) *(float2*)&C[(size_t)r * Ncols + c] =
                make_float2(acc[mi][ni][2], acc[mi][ni][3]);
        }
}

__global__ __launch_bounds__(256, 2)
void gemm_mma(const __nv_bfloat16* __restrict__ A,
              const __nv_bfloat16* __restrict__ Bm,
              float* __restrict__ C, int M, int Ncols, int nkt) {
    extern __shared__ char dyn[];
    gemm_body(A, Bm, C + (size_t)blockIdx.z * M * Ncols, M, Ncols,
              nkt, blockIdx.z * nkt, blockIdx.y, blockIdx.x, dyn);
}

// ---------------------------------------------------------------------------
// Split-K reduction: C[i] = sum_{z<KSPL} P[z*elems + i]. float4 vectorized.
// ---------------------------------------------------------------------------
template <int KSPL>
__global__ void reduce_k(const float* __restrict__ P, float* __restrict__ C,
                         int elems4) {
    const int i = blockIdx.x * 256 + threadIdx.x;
    if (i >= elems4) return;
    const float4* p = (const float4*)P;
    float4 v = p[i];
#pragma unroll
    for (int z = 1; z < KSPL; z++) {
        const float4 u = p[(size_t)z * elems4 + i];
        v.x += u.x; v.y += u.y; v.z += u.z; v.w += u.w;
    }
    ((float4*)C)[i] = v;
}

// ---------------------------------------------------------------------------
// Row LayerNorm over MID_=4096, in place, float4-vectorized.
// ---------------------------------------------------------------------------
__global__ void ln_kernel(float* __restrict__ mid,
                          const float* __restrict__ g,
                          const float* __restrict__ bt) {
    const int row = blockIdx.x;
    float4* p = (float4*)(mid + (size_t)row * MID_);
    const float4* g4 = (const float4*)g;
    const float4* b4 = (const float4*)bt;
    const int tid = threadIdx.x;
    const int lane = tid & 31, warp = tid >> 5;

    float4 v[4];
    float s = 0.f, ss = 0.f;
#pragma unroll
    for (int j = 0; j < 4; j++) {
        v[j] = p[tid + (j << 8)];
        s  += v[j].x + v[j].y + v[j].z + v[j].w;
        ss += v[j].x * v[j].x + v[j].y * v[j].y + v[j].z * v[j].z + v[j].w * v[j].w;
    }
#pragma unroll
    for (int off = 16; off; off >>= 1) {
        s  += __shfl_xor_sync(~0u, s,  off);
        ss += __shfl_xor_sync(~0u, ss, off);
    }
    __shared__ float rs[8], rss[8];
    if (lane == 0) { rs[warp] = s; rss[warp] = ss; }
    __syncthreads();
    s = 0.f; ss = 0.f;
#pragma unroll
    for (int k = 0; k < 8; k++) { s += rs[k]; ss += rss[k]; }
    const float mu  = s * (1.f / MID_);
    const float var = ss * (1.f / MID_) - mu * mu;
    const float inv = rsqrtf(var + 1e-5f);
#pragma unroll
    for (int j = 0; j < 4; j++) {
        const int idx = tid + (j << 8);
        const float4 gv = g4[idx], bv = b4[idx];
        float4 o;
        o.x = (v[j].x - mu) * inv * gv.x + bv.x;
        o.y = (v[j].y - mu) * inv * gv.y + bv.y;
        o.z = (v[j].z - mu) * inv * gv.z + bv.z;
        o.w = (v[j].w - mu) * inv * gv.w + bv.w;
        p[idx] = o;
    }
}

// ---------------------------------------------------------------------------
// Attention + rank-space contraction (fp32-exact).
// ---------------------------------------------------------------------------
__global__ void attn_w_kernel(const float* __restrict__ qb,
                              const float* __restrict__ kb,
                              const float* __restrict__ mid,
                              float* __restrict__ w) {
    const int i = blockIdx.x;
    const int h = blockIdx.y;
    const int b = blockIdx.z;
    const int tid = threadIdx.x;
    const int lane = tid & 31, warp = tid >> 5;

    __shared__ float qs[DH_];
    __shared__ float sim[N_];
    __shared__ float red8[8];
    __shared__ float wred[4][R_];
    __shared__ float s_total;

    if (tid < DH_) qs[tid] = qb[((size_t)(b * NQ_ + i)) * D_ + h * DH_ + tid];
    __syncthreads();

    for (int n = warp; n < N_; n += 8) {
        const float* kp = kb + ((size_t)(b * N_ + n)) * D_ + h * DH_;
        float acc = 0.f;
#pragma unroll
        for (int d = lane; d < DH_; d += 32) acc += qs[d] * kp[d];
#pragma unroll
        for (int off = 16; off; off >>= 1) acc += __shfl_xor_sync(~0u, acc, off);
        if (lane == 0) sim[n] = acc * 0.0883883476483184406f;
    }
    __syncthreads();

    float m = -1e30f;
    for (int n = tid; n < N_; n += 256) m = fmaxf(m, sim[n]);
#pragma unroll
    for (int off = 16; off; off >>= 1) m = fmaxf(m, __shfl_xor_sync(~0u, m, off));
    if (lane == 0) red8[warp] = m;
    __syncthreads();
    float mm = red8[0];
#pragma unroll
    for (int k = 1; k < 8; k++) mm = fmaxf(mm, red8[k]);
    __syncthreads();

    float s = 0.f;
    for (int n = tid; n < N_; n += 256) {
        const float e = __expf(sim[n] - mm);
        sim[n] = e;
        s += e;
    }
#pragma unroll
    for (int off = 16; off; off >>= 1) s += __shfl_xor_sync(~0u, s, off);
    if (lane == 0) red8[warp] = s;
    __syncthreads();
    if (tid == 0) {
        float t = 0.f;
#pragma unroll
        for (int k = 0; k < 8; k++) t += red8[k];
        s_total = 1.f / t;
    }
    __syncthreads();

    const int r = tid & 63, grp = tid >> 6;
    float acc = 0.f;
    for (int n = grp; n < N_; n += 4)
        acc += sim[n] * mid[((size_t)(b * N_ + n)) * MID_ + i * R_ + r];
    wred[grp][r] = acc;
    __syncthreads();
    if (grp == 0) {
        const float v = (wred[0][r] + wred[1][r] + wred[2][r] + wred[3][r]) * s_total;
        w[(((size_t)b * H_ + h) * NQ_ + i) * R_ + r] = v;
    }
}

// ---------------------------------------------------------------------------
// Rank expansion: outpre[b,i,d] = sum_r Wconv[i,d,r] * w[b, d/128, i, r]
// ---------------------------------------------------------------------------
__global__ void convout_kernel(const float* __restrict__ w,
                               const float* __restrict__ Wconv,
                               float* __restrict__ outpre) {
    const int i = blockIdx.x % NQ_;
    const int b = blockIdx.x / NQ_;
    const int tid = threadIdx.x;

    __shared__ float ws[H_ * R_];
    for (int j = tid; j < H_ * R_; j += 256)
        ws[j] = w[(((size_t)b * H_ + (j >> 6)) * NQ_ + i) * R_ + (j & 63)];
    __syncthreads();

    for (int d = tid; d < D_; d += 256) {
        const float* wc = Wconv + ((size_t)i * D_ + d) * R_;
        const float* wv = &ws[(d >> 7) * R_];
        float acc = 0.f;
#pragma unroll
        for (int r = 0; r < R_; r += 4) {
            const float4 c4 = *(const float4*)&wc[r];
            acc += c4.x * wv[r] + c4.y * wv[r + 1] + c4.z * wv[r + 2] + c4.w * wv[r + 3];
        }
        outpre[((size_t)b * NQ_ + i) * D_ + d] = acc;
    }
}

// ---------------------------------------------------------------------------
extern "C" void kernel_launch(void* const* d_in, const int* in_sizes, int n_in,
                              void* d_out, int out_size) {
    const float* x     = (const float*)d_in[0];
    const float* ctx   = (const float*)d_in[1];
    const float* Wq    = (const float*)d_in[2];
    const float* Wk    = (const float*)d_in[3];
    const float* Wv1   = (const float*)d_in[4];
    const float* ln_g  = (const float*)d_in[5];
    const float* ln_b  = (const float*)d_in[6];
    const float* Wconv = (const float*)d_in[7];
    const float* Wout  = (const float*)d_in[8];
    float* out = (float*)d_out;

    __nv_bfloat16 *Wout2, *op2;
    float *qp, *kp, *midp, *wp, *opp, *pp;
    cudaGetSymbolAddress((void**)&Wout2,g_Wout2);
    cudaGetSymbolAddress((void**)&op2,  g_op2);
    cudaGetSymbolAddress((void**)&qp,   g_q);
    cudaGetSymbolAddress((void**)&kp,   g_k);
    cudaGetSymbolAddress((void**)&midp, g_mid);
    cudaGetSymbolAddress((void**)&wp,   g_w);
    cudaGetSymbolAddress((void**)&opp,  g_outpre);
    cudaGetSymbolAddress((void**)&pp,   g_part);
    float* kpart = pp;
    float* qpart = pp + 2 * (size_t)BN_ROWS * D_;

    const int SMEM = 3 * STG_BYTES;   // 98304
    cudaFuncSetAttribute(gemm_fused_tf32, cudaFuncAttributeMaxDynamicSharedMemorySize, SMEM);
    cudaFuncSetAttribute(gemm_mma,        cudaFuncAttributeMaxDynamicSharedMemorySize, SMEM);

    const int T = 256;
    auto blks = [](int n) { return (n + 255) / 256; };

    // Wout split (only remaining bf16 weight prep)
    split_kernel<1><<<blks(D_ * D_ / 4), T>>>(Wout, Wout2, D_);

    // ONE tf32 launch: mid + k(split2) + q(split4), 844 CTAs, fp32 inputs
    gemm_fused_tf32<<<TOT_TILES, T, SMEM>>>(ctx, Wv1, midp, Wk, kpart, x, Wq, qpart);
    reduce_k<4><<<blks(BQ_ROWS * D_ / 4), T>>>(qpart, qp, BQ_ROWS * D_ / 4);
    reduce_k<2><<<blks(BN_ROWS * D_ / 4), T>>>(kpart, kp, BN_ROWS * D_ / 4);

    ln_kernel<<<BN_ROWS, 256>>>(midp, ln_g, ln_b);
    attn_w_kernel<<<dim3(NQ_, H_, B_), 256>>>(qp, kp, midp, wp);
    convout_kernel<<<BQ_ROWS, 256>>>(wp, Wconv, opp);

    // final = outpre @ Wout^T (512 x 768): split-bf16 3-term, split-K=4
    split_kernel<0><<<blks(BQ_ROWS * D_ / 4), T>>>(opp, op2, BQ_ROWS);
    gemm_mma<<<dim3(D_ / 128, BQ_ROWS / 128, 4), T, SMEM>>>(
        op2, Wout2, pp, BQ_ROWS, D_, NKT / 4);
    reduce_k<4><<<blks(BQ_ROWS * D_ / 4), T>>>(pp, out, BQ_ROWS * D_ / 4);
}

// round 10
// speedup vs baseline: 1.9591x; 1.1542x over previous
#include <cuda_runtime.h>
#include <cuda_bf16.h>
#include <cstdint>

#define B_   8
#define NQ_  64
#define N_   257
#define D_   768
#define H_   6
#define R_   64
#define DH_  128
#define MID_ 4096
#define BN_ROWS 2056
#define BQ_ROWS 512
#define K3  (3 * D_)          // 2304: split-bf16 K (out-GEMM only)
#define NKT (K3 / 64)         // 36 bf16 k-tiles
#define NKT32 (D_ / 32)       // 24 tf32 k-tiles

// fused-GEMM job boundaries (tf32 path)
#define MID_TILES 544          // 17 m-tiles x 32 n-tiles, 24 iters
#define KQ_B0     544          // k: 2 z x 17 x 6 = 204, 12 iters
#define Q_B0      748          // q: 4 z x 4 x 6  = 96,  6 iters
#define TOT_TILES 844

// pre-round segment sizes (float4 units)
#define X4    (BQ_ROWS * D_ / 4)        // 98304
#define CTX4  (BN_ROWS * D_ / 4)        // 394752
#define W4    (D_ * D_ / 4)             // 147456
#define WV14  (MID_ * D_ / 4)           // 786432
#define TOT4  (X4 + CTX4 + 2 * W4 + WV14)

// ---------------- scratch (device globals; no allocation allowed) ----------
__device__ __align__(256) float g_rnd[(size_t)TOT4 * 4];   // tf32-rounded inputs
__device__ __align__(256) __nv_bfloat16 g_Wout2[D_  * (size_t)K3];
__device__ __align__(256) __nv_bfloat16 g_op2 [BQ_ROWS * (size_t)K3];
__device__ float g_q[BQ_ROWS * (size_t)D_];
__device__ float g_k[BN_ROWS * (size_t)D_];
__device__ float g_mid[BN_ROWS * (size_t)MID_];
__device__ float g_w[(size_t)B_ * H_ * NQ_ * R_];
__device__ float g_outpre[BQ_ROWS * (size_t)D_];
// k partials (2 x 2056 x 768) then q partials (4 x 512 x 768)
__device__ float g_part[2 * BN_ROWS * (size_t)D_ + 4 * BQ_ROWS * (size_t)D_];

// ---------------------------- PTX helpers ----------------------------------
__device__ __forceinline__ unsigned smem_u32(const void* p) {
    return (unsigned)__cvta_generic_to_shared(p);
}
#define CPA16(dst_u32, src_ptr) \
    asm volatile("cp.async.cg.shared.global [%0], [%1], 16;\n" :: "r"(dst_u32), "l"(src_ptr))
#define LDSM_X4(r0, r1, r2, r3, addr) \
    asm volatile("ldmatrix.sync.aligned.m8n8.x4.shared.b16 {%0,%1,%2,%3}, [%4];" \
                 : "=r"(r0), "=r"(r1), "=r"(r2), "=r"(r3) : "r"(addr))
#define MMA16816(acc, a, b0, b1) \
    asm volatile( \
        "mma.sync.aligned.m16n8k16.row.col.f32.bf16.bf16.f32 " \
        "{%0,%1,%2,%3}, {%4,%5,%6,%7}, {%8,%9}, {%0,%1,%2,%3};\n" \
        : "+f"((acc)[0]), "+f"((acc)[1]), "+f"((acc)[2]), "+f"((acc)[3]) \
        : "r"((a)[0]), "r"((a)[1]), "r"((a)[2]), "r"((a)[3]), "r"(b0), "r"(b1))
#define MMA1688_TF32(acc, a, b) \
    asm volatile( \
        "mma.sync.aligned.m16n8k8.row.col.f32.tf32.tf32.f32 " \
        "{%0,%1,%2,%3}, {%4,%5,%6,%7}, {%8,%9}, {%0,%1,%2,%3};\n" \
        : "+f"((acc)[0]), "+f"((acc)[1]), "+f"((acc)[2]), "+f"((acc)[3]) \
        : "r"((a)[0]), "r"((a)[1]), "r"((a)[2]), "r"((a)[3]), \
          "r"((b)[0]), "r"((b)[1]))

__device__ __forceinline__ uint32_t sw128(uint32_t off) {
    return off ^ ((off >> 3) & 0x70);
}
__device__ __forceinline__ float rna_tf32(float v) {
    uint32_t t;
    asm("cvt.rna.tf32.f32 %0, %1;" : "=r"(t) : "f"(v));
    return __uint_as_float(t);
}

// ---------------------------------------------------------------------------
// Pre-round all tf32-GEMM inputs to tf32 (RNA) into g_rnd (one flat pass).
// Segment order: x | ctx | Wq | Wk | Wv1.
// ---------------------------------------------------------------------------
__global__ void round_tf32_kernel(const float* __restrict__ x,
                                  const float* __restrict__ ctx,
                                  const float* __restrict__ Wq,
                                  const float* __restrict__ Wk,
                                  const float* __restrict__ Wv1,
                                  float* __restrict__ Y) {
    const int i = blockIdx.x * 256 + threadIdx.x;
    if (i >= TOT4) return;
    int j = i;
    const float4* src;
    if (j < X4)                  src = (const float4*)x;
    else if ((j -= X4) < CTX4)   src = (const float4*)ctx;
    else if ((j -= CTX4) < W4)   src = (const float4*)Wq;
    else if ((j -= W4) < W4)     src = (const float4*)Wk;
    else { j -= W4;              src = (const float4*)Wv1; }
    float4 v = src[j];
    v.x = rna_tf32(v.x); v.y = rna_tf32(v.y);
    v.z = rna_tf32(v.z); v.w = rna_tf32(v.w);
    ((float4*)Y)[i] = v;
}

// ---------------------------------------------------------------------------
// Split fp32 -> bf16 hi/lo (out-GEMM path only).
// MODE 0 (A-side): [hi | hi | lo]   MODE 1 (B-side): [hi | lo | hi]
// ---------------------------------------------------------------------------
__device__ __forceinline__ void split_store4(float4 v, __nv_bfloat16* Y, size_t base,
                                             int mode) {
    __nv_bfloat16 h[4], l[4];
    const float xs[4] = {v.x, v.y, v.z, v.w};
#pragma unroll
    for (int j = 0; j < 4; j++) {
        h[j] = __float2bfloat16(xs[j]);
        l[j] = __float2bfloat16(xs[j] - __bfloat162float(h[j]));
    }
    __nv_bfloat162* y0 = (__nv_bfloat162*)(Y + base);
    __nv_bfloat162* y1 = (__nv_bfloat162*)(Y + base + D_);
    __nv_bfloat162* y2 = (__nv_bfloat162*)(Y + base + 2 * D_);
    const __nv_bfloat162 hp0 = {h[0], h[1]}, hp1 = {h[2], h[3]};
    const __nv_bfloat162 lp0 = {l[0], l[1]}, lp1 = {l[2], l[3]};
    y0[0] = hp0; y0[1] = hp1;
    if (mode == 0) { y1[0] = hp0; y1[1] = hp1; y2[0] = lp0; y2[1] = lp1; }
    else           { y1[0] = lp0; y1[1] = lp1; y2[0] = hp0; y2[1] = hp1; }
}

template <int MODE>
__global__ void split_kernel(const float* __restrict__ X,
                             __nv_bfloat16* __restrict__ Y, int M) {
    const int i = blockIdx.x * 256 + threadIdx.x;
    if (i >= M * (D_ / 4)) return;
    const int row = i / (D_ / 4), c4 = i - row * (D_ / 4);
    split_store4(((const float4*)X)[i], Y, (size_t)row * K3 + c4 * 4, MODE);
}

// ---------------------------------------------------------------------------
// TF32 GEMM body, 128x128 tile: C = A[M,768] @ B[N,768]^T (A,B pre-rounded).
// BK=32 fp32 (128B rows), 3-stage cp.async, 256 thr = 8 warps (4M x 2N).
// Fragments loaded via ldmatrix.x4 (8x4-tf32 tiles == 8x8-b16 tiles).
// ---------------------------------------------------------------------------
#define STG_BYTES 32768            // (128 + 128) rows * 128 B

__device__ __forceinline__
void gemm_body_tf32(const float* __restrict__ A,
                    const float* __restrict__ Bm,
                    float* __restrict__ C, int M, int Ncols,
                    int nkt, int kt0, int mt, int nt, char* dyn) {
    const uint32_t base = smem_u32(dyn);

    const int tid = threadIdx.x;
    const int warp = tid >> 5, lane = tid & 31;
    const int wm = warp & 3, wn = warp >> 2;
    const int gr = lane >> 2, tig = lane & 3;
    const int lrow = lane & 7, lmat = lane >> 3;      // ldmatrix row/matrix
    const int m0 = mt * 128, n0 = nt * 128;

    float acc[2][8][4];
#pragma unroll
    for (int mi = 0; mi < 2; mi++)
#pragma unroll
        for (int ni = 0; ni < 8; ni++)
#pragma unroll
            for (int j = 0; j < 4; j++) acc[mi][ni][j] = 0.f;

    auto load_stage = [&](int kt) {
        const uint32_t sb = base + (kt % 3) * STG_BYTES;
        const int k0 = (kt0 + kt) * 32;           // fp32 col offset
#pragma unroll
        for (int i = 0; i < 4; i++) {             // A: 128 rows x 128B
            const int c = tid + i * 256;
            const int row = c >> 3, c16 = c & 7;
            int grow = m0 + row; if (grow >= M) grow = M - 1;
            CPA16(sb + sw128((uint32_t)(row * 128 + c16 * 16)),
                  A + (size_t)grow * D_ + k0 + c16 * 4);
        }
#pragma unroll
        for (int i = 0; i < 4; i++) {             // B: 128 rows x 128B
            const int c = tid + i * 256;
            const int row = c >> 3, c16 = c & 7;
            CPA16(sb + 16384 + sw128((uint32_t)(row * 128 + c16 * 16)),
                  Bm + (size_t)(n0 + row) * D_ + k0 + c16 * 4);
        }
        asm volatile("cp.async.commit_group;\n" ::);
    };

    load_stage(0);
    load_stage(1);

    for (int kt = 0; kt < nkt; kt++) {
        const int s = kt % 3;
        asm volatile("cp.async.wait_group 1;\n" ::);
        __syncthreads();
        if (kt + 2 < nkt) load_stage(kt + 2);
        else asm volatile("cp.async.commit_group;\n" ::);

        const uint32_t sA = base + s * STG_BYTES;
        const uint32_t sB = sA + 16384;
#pragma unroll
        for (int kk = 0; kk < 4; kk++) {
            const int kb = kk * 32;               // byte base of 8-wide k group
            uint32_t a[2][4], b[8][2];
            // A: x4 = (rows±8) x (k±4) sub-tiles; reg order matches a0..a3
#pragma unroll
            for (int mi = 0; mi < 2; mi++) {
                const int r = wm * 32 + mi * 16 + ((lmat & 1) << 3) + lrow;
                LDSM_X4(a[mi][0], a[mi][1], a[mi][2], a[mi][3],
                        sA + sw128((uint32_t)(r * 128 + kb + ((lmat >> 1) << 4))));
            }
            // B: x4 covers two 8-wide n groups x (k±4)
#pragma unroll
            for (int gp = 0; gp < 4; gp++) {
                const int n = wn * 64 + gp * 16 + ((lmat >> 1) << 3) + lrow;
                LDSM_X4(b[2 * gp][0], b[2 * gp][1], b[2 * gp + 1][0], b[2 * gp + 1][1],
                        sB + sw128((uint32_t)(n * 128 + kb + ((lmat & 1) << 4))));
            }
#pragma unroll
            for (int mi = 0; mi < 2; mi++)
#pragma unroll
                for (int ni = 0; ni < 8; ni++)
                    MMA1688_TF32(acc[mi][ni], a[mi], b[ni]);
        }
    }

#pragma unroll
    for (int mi = 0; mi < 2; mi++)
#pragma unroll
        for (int ni = 0; ni < 8; ni++) {
            const int c = n0 + wn * 64 + ni * 8 + 2 * tig;
            int r = m0 + wm * 32 + mi * 16 + gr;
            if (r < M) *(float2*)&C[(size_t)r * Ncols + c] =
                make_float2(acc[mi][ni][0], acc[mi][ni][1]);
            r += 8;
            if (r < M) *(float2*)&C[(size_t)r * Ncols + c] =
                make_float2(acc[mi][ni][2], acc[mi][ni][3]);
        }
}

// Fused tf32 launch: mid + k (split-K2) + q (split-K4), one grid.
__global__ __launch_bounds__(256, 2)
void gemm_fused_tf32(const float* __restrict__ ctx,
                     const float* __restrict__ Wv1, float* __restrict__ midp,
                     const float* __restrict__ Wk,  float* __restrict__ kpart,
                     const float* __restrict__ x,
                     const float* __restrict__ Wq,  float* __restrict__ qpart) {
    extern __shared__ char dyn[];
    const int bid = blockIdx.x;
    if (bid < MID_TILES) {
        gemm_body_tf32(ctx, Wv1, midp, BN_ROWS, MID_, NKT32, 0,
                       bid / 32, bid % 32, dyn);
    } else if (bid < Q_B0) {
        const int t = bid - KQ_B0;
        const int z = t / 102, r = t - z * 102;       // 17 x 6 tiles
        gemm_body_tf32(ctx, Wk, kpart + (size_t)z * BN_ROWS * D_, BN_ROWS, D_,
                       NKT32 / 2, z * (NKT32 / 2), r / 6, r % 6, dyn);
    } else {
        const int t = bid - Q_B0;
        const int z = t / 24, r = t - z * 24;         // 4 x 6 tiles
        gemm_body_tf32(x, Wq, qpart + (size_t)z * BQ_ROWS * D_, BQ_ROWS, D_,
                       NKT32 / 4, z * (NKT32 / 4), r / 6, r % 6, dyn);
    }
}

// ---------------------------------------------------------------------------
// bf16 split GEMM body (out-GEMM only): C = A[M,K3] @ B[N,K3]^T.
// ---------------------------------------------------------------------------
__device__ __forceinline__
void gemm_body(const __nv_bfloat16* __restrict__ A,
               const __nv_bfloat16* __restrict__ Bm,
               float* __restrict__ C, int M, int Ncols,
               int nkt, int kt0, int mt, int nt, char* dyn) {
    const uint32_t base = smem_u32(dyn);

    const int tid = threadIdx.x;
    const int warp = tid >> 5, lane = tid & 31;
    const int wm = warp & 3, wn = warp >> 2;
    const int gr = lane >> 2, tig = lane & 3;
    const int m0 = mt * 128, n0 = nt * 128;

    const int a_r = (lane & 7) + ((lane >> 3) & 1) * 8;
    const int a_k = (lane >> 4) * 8;
    const int b_c = (lane & 7) + ((lane >> 4) & 1) * 8;
    const int b_k = ((lane >> 3) & 1) * 8;

    float acc[2][8][4];
#pragma unroll
    for (int mi = 0; mi < 2; mi++)
#pragma unroll
        for (int ni = 0; ni < 8; ni++)
#pragma unroll
            for (int j = 0; j < 4; j++) acc[mi][ni][j] = 0.f;

    auto load_stage = [&](int kt) {
        const uint32_t sb = base + (kt % 3) * STG_BYTES;
        const int k0 = (kt0 + kt) * 64;
#pragma unroll
        for (int i = 0; i < 4; i++) {
            const int c = tid + i * 256;
            const int row = c >> 3, c16 = c & 7;
            int grow = m0 + row; if (grow >= M) grow = M - 1;
            CPA16(sb + sw128((uint32_t)(row * 128 + c16 * 16)),
                  A + (size_t)grow * K3 + k0 + c16 * 8);
        }
#pragma unroll
        for (int i = 0; i < 4; i++) {
            const int c = tid + i * 256;
            const int row = c >> 3, c16 = c & 7;
            CPA16(sb + 16384 + sw128((uint32_t)(row * 128 + c16 * 16)),
                  Bm + (size_t)(n0 + row) * K3 + k0 + c16 * 8);
        }
        asm volatile("cp.async.commit_group;\n" ::);
    };

    load_stage(0);
    load_stage(1);

    for (int kt = 0; kt < nkt; kt++) {
        const int s = kt % 3;
        asm volatile("cp.async.wait_group 1;\n" ::);
        __syncthreads();
        if (kt + 2 < nkt) load_stage(kt + 2);
        else asm volatile("cp.async.commit_group;\n" ::);

        const uint32_t sA = base + s * STG_BYTES;
        const uint32_t sB = sA + 16384;
#pragma unroll
        for (int kk = 0; kk < 4; kk++) {
            const int k16 = kk * 16;
            uint32_t a[2][4], b[4][4];
#pragma unroll
            for (int mi = 0; mi < 2; mi++) {
                const int r = wm * 32 + mi * 16 + a_r;
                LDSM_X4(a[mi][0], a[mi][1], a[mi][2], a[mi][3],
                        sA + sw128((uint32_t)(r * 128 + (k16 + a_k) * 2)));
            }
#pragma unroll
            for (int nj = 0; nj < 4; nj++) {
                const int cth = wn * 64 + nj * 16 + b_c;
                LDSM_X4(b[nj][0], b[nj][1], b[nj][2], b[nj][3],
                        sB + sw128((uint32_t)(cth * 128 + (k16 + b_k) * 2)));
            }
#pragma unroll
            for (int mi = 0; mi < 2; mi++)
#pragma unroll
                for (int ni = 0; ni < 8; ni++)
                    MMA16816(acc[mi][ni], a[mi],
                             b[ni >> 1][(ni & 1) * 2], b[ni >> 1][(ni & 1) * 2 + 1]);
        }
    }

#pragma unroll
    for (int mi = 0; mi < 2; mi++)
#pragma unroll
        for (int ni = 0; ni < 8; ni++) {
            const int c = n0 + wn * 64 + ni * 8 + 2 * tig;
            int r = m0 + wm * 32 + mi * 16 + gr;
            if (r < M) *(float2*)&C[(size_t)r * Ncols + c] =
                make_float2(acc[mi][ni][0], acc[mi][ni][1]);
            r += 8;
            if (r < M) *(float2*)&C[(size_t)r * Ncols + c] =
                make_float2(acc[mi][ni][2], acc[mi][ni][3]);
        }
}

__global__ __launch_bounds__(256, 2)
void gemm_mma(const __nv_bfloat16* __restrict__ A,
              const __nv_bfloat16* __restrict__ Bm,
              float* __restrict__ C, int M, int Ncols, int nkt) {
    extern __shared__ char dyn[];
    gemm_body(A, Bm, C + (size_t)blockIdx.z * M * Ncols, M, Ncols,
              nkt, blockIdx.z * nkt, blockIdx.y, blockIdx.x, dyn);
}

// ---------------------------------------------------------------------------
// Split-K reduction: C[i] = sum_{z<KSPL} P[z*elems + i]. float4 vectorized.
// ---------------------------------------------------------------------------
template <int KSPL>
__global__ void reduce_k(const float* __restrict__ P, float* __restrict__ C,
                         int elems4) {
    const int i = blockIdx.x * 256 + threadIdx.x;
    if (i >= elems4) return;
    const float4* p = (const float4*)P;
    float4 v = p[i];
#pragma unroll
    for (int z = 1; z < KSPL; z++) {
        const float4 u = p[(size_t)z * elems4 + i];
        v.x += u.x; v.y += u.y; v.z += u.z; v.w += u.w;
    }
    ((float4*)C)[i] = v;
}

// ---------------------------------------------------------------------------
// Row LayerNorm over MID_=4096, in place, float4-vectorized.
// ---------------------------------------------------------------------------
__global__ void ln_kernel(float* __restrict__ mid,
                          const float* __restrict__ g,
                          const float* __restrict__ bt) {
    const int row = blockIdx.x;
    float4* p = (float4*)(mid + (size_t)row * MID_);
    const float4* g4 = (const float4*)g;
    const float4* b4 = (const float4*)bt;
    const int tid = threadIdx.x;
    const int lane = tid & 31, warp = tid >> 5;

    float4 v[4];
    float s = 0.f, ss = 0.f;
#pragma unroll
    for (int j = 0; j < 4; j++) {
        v[j] = p[tid + (j << 8)];
        s  += v[j].x + v[j].y + v[j].z + v[j].w;
        ss += v[j].x * v[j].x + v[j].y * v[j].y + v[j].z * v[j].z + v[j].w * v[j].w;
    }
#pragma unroll
    for (int off = 16; off; off >>= 1) {
        s  += __shfl_xor_sync(~0u, s,  off);
        ss += __shfl_xor_sync(~0u, ss, off);
    }
    __shared__ float rs[8], rss[8];
    if (lane == 0) { rs[warp] = s; rss[warp] = ss; }
    __syncthreads();
    s = 0.f; ss = 0.f;
#pragma unroll
    for (int k = 0; k < 8; k++) { s += rs[k]; ss += rss[k]; }
    const float mu  = s * (1.f / MID_);
    const float var = ss * (1.f / MID_) - mu * mu;
    const float inv = rsqrtf(var + 1e-5f);
#pragma unroll
    for (int j = 0; j < 4; j++) {
        const int idx = tid + (j << 8);
        const float4 gv = g4[idx], bv = b4[idx];
        float4 o;
        o.x = (v[j].x - mu) * inv * gv.x + bv.x;
        o.y = (v[j].y - mu) * inv * gv.y + bv.y;
        o.z = (v[j].z - mu) * inv * gv.z + bv.z;
        o.w = (v[j].w - mu) * inv * gv.w + bv.w;
        p[idx] = o;
    }
}

// ---------------------------------------------------------------------------
// Attention + rank-space contraction (fp32-exact).
// ---------------------------------------------------------------------------
__global__ void attn_w_kernel(const float* __restrict__ qb,
                              const float* __restrict__ kb,
                              const float* __restrict__ mid,
                              float* __restrict__ w) {
    const int i = blockIdx.x;
    const int h = blockIdx.y;
    const int b = blockIdx.z;
    const int tid = threadIdx.x;
    const int lane = tid & 31, warp = tid >> 5;

    __shared__ float qs[DH_];
    __shared__ float sim[N_];
    __shared__ float red8[8];
    __shared__ float wred[4][R_];
    __shared__ float s_total;

    if (tid < DH_) qs[tid] = qb[((size_t)(b * NQ_ + i)) * D_ + h * DH_ + tid];
    __syncthreads();

    for (int n = warp; n < N_; n += 8) {
        const float* kp = kb + ((size_t)(b * N_ + n)) * D_ + h * DH_;
        float acc = 0.f;
#pragma unroll
        for (int d = lane; d < DH_; d += 32) acc += qs[d] * kp[d];
#pragma unroll
        for (int off = 16; off; off >>= 1) acc += __shfl_xor_sync(~0u, acc, off);
        if (lane == 0) sim[n] = acc * 0.0883883476483184406f;
    }
    __syncthreads();

    float m = -1e30f;
    for (int n = tid; n < N_; n += 256) m = fmaxf(m, sim[n]);
#pragma unroll
    for (int off = 16; off; off >>= 1) m = fmaxf(m, __shfl_xor_sync(~0u, m, off));
    if (lane == 0) red8[warp] = m;
    __syncthreads();
    float mm = red8[0];
#pragma unroll
    for (int k = 1; k < 8; k++) mm = fmaxf(mm, red8[k]);
    __syncthreads();

    float s = 0.f;
    for (int n = tid; n < N_; n += 256) {
        const float e = __expf(sim[n] - mm);
        sim[n] = e;
        s += e;
    }
#pragma unroll
    for (int off = 16; off; off >>= 1) s += __shfl_xor_sync(~0u, s, off);
    if (lane == 0) red8[warp] = s;
    __syncthreads();
    if (tid == 0) {
        float t = 0.f;
#pragma unroll
        for (int k = 0; k < 8; k++) t += red8[k];
        s_total = 1.f / t;
    }
    __syncthreads();

    const int r = tid & 63, grp = tid >> 6;
    float acc = 0.f;
    for (int n = grp; n < N_; n += 4)
        acc += sim[n] * mid[((size_t)(b * N_ + n)) * MID_ + i * R_ + r];
    wred[grp][r] = acc;
    __syncthreads();
    if (grp == 0) {
        const float v = (wred[0][r] + wred[1][r] + wred[2][r] + wred[3][r]) * s_total;
        w[(((size_t)b * H_ + h) * NQ_ + i) * R_ + r] = v;
    }
}

// ---------------------------------------------------------------------------
// Rank expansion: outpre[b,i,d] = sum_r Wconv[i,d,r] * w[b, d/128, i, r]
// ---------------------------------------------------------------------------
__global__ void convout_kernel(const float* __restrict__ w,
                               const float* __restrict__ Wconv,
                               float* __restrict__ outpre) {
    const int i = blockIdx.x % NQ_;
    const int b = blockIdx.x / NQ_;
    const int tid = threadIdx.x;

    __shared__ float ws[H_ * R_];
    for (int j = tid; j < H_ * R_; j += 256)
        ws[j] = w[(((size_t)b * H_ + (j >> 6)) * NQ_ + i) * R_ + (j & 63)];
    __syncthreads();

    for (int d = tid; d < D_; d += 256) {
        const float* wc = Wconv + ((size_t)i * D_ + d) * R_;
        const float* wv = &ws[(d >> 7) * R_];
        float acc = 0.f;
#pragma unroll
        for (int r = 0; r < R_; r += 4) {
            const float4 c4 = *(const float4*)&wc[r];
            acc += c4.x * wv[r] + c4.y * wv[r + 1] + c4.z * wv[r + 2] + c4.w * wv[r + 3];
        }
        outpre[((size_t)b * NQ_ + i) * D_ + d] = acc;
    }
}

// ---------------------------------------------------------------------------
extern "C" void kernel_launch(void* const* d_in, const int* in_sizes, int n_in,
                              void* d_out, int out_size) {
    const float* x     = (const float*)d_in[0];
    const float* ctx   = (const float*)d_in[1];
    const float* Wq    = (const float*)d_in[2];
    const float* Wk    = (const float*)d_in[3];
    const float* Wv1   = (const float*)d_in[4];
    const float* ln_g  = (const float*)d_in[5];
    const float* ln_b  = (const float*)d_in[6];
    const float* Wconv = (const float*)d_in[7];
    const float* Wout  = (const float*)d_in[8];
    float* out = (float*)d_out;

    __nv_bfloat16 *Wout2, *op2;
    float *qp, *kp, *midp, *wp, *opp, *pp, *rnd;
    cudaGetSymbolAddress((void**)&Wout2,g_Wout2);
    cudaGetSymbolAddress((void**)&op2,  g_op2);
    cudaGetSymbolAddress((void**)&qp,   g_q);
    cudaGetSymbolAddress((void**)&kp,   g_k);
    cudaGetSymbolAddress((void**)&midp, g_mid);
    cudaGetSymbolAddress((void**)&wp,   g_w);
    cudaGetSymbolAddress((void**)&opp,  g_outpre);
    cudaGetSymbolAddress((void**)&pp,   g_part);
    cudaGetSymbolAddress((void**)&rnd,  g_rnd);
    float* kpart = pp;
    float* qpart = pp + 2 * (size_t)BN_ROWS * D_;
    float* x_r   = rnd;
    float* ctx_r = x_r + (size_t)X4 * 4;
    float* Wq_r  = ctx_r + (size_t)CTX4 * 4;
    float* Wk_r  = Wq_r + (size_t)W4 * 4;
    float* Wv1_r = Wk_r + (size_t)W4 * 4;

    const int SMEM = 3 * STG_BYTES;   // 98304
    cudaFuncSetAttribute(gemm_fused_tf32, cudaFuncAttributeMaxDynamicSharedMemorySize, SMEM);
    cudaFuncSetAttribute(gemm_mma,        cudaFuncAttributeMaxDynamicSharedMemorySize, SMEM);

    const int T = 256;
    auto blks = [](int n) { return (n + 255) / 256; };

    // pre-round all tf32-GEMM inputs (RNA) + Wout bf16 split
    round_tf32_kernel<<<blks(TOT4), T>>>(x, ctx, Wq, Wk, Wv1, rnd);
    split_kernel<1><<<blks(D_ * D_ / 4), T>>>(Wout, Wout2, D_);

    // ONE tf32 launch: mid + k(split2) + q(split4), 844 CTAs
    gemm_fused_tf32<<<TOT_TILES, T, SMEM>>>(ctx_r, Wv1_r, midp, Wk_r, kpart,
                                            x_r, Wq_r, qpart);
    reduce_k<4><<<blks(BQ_ROWS * D_ / 4), T>>>(qpart, qp, BQ_ROWS * D_ / 4);
    reduce_k<2><<<blks(BN_ROWS * D_ / 4), T>>>(kpart, kp, BN_ROWS * D_ / 4);

    ln_kernel<<<BN_ROWS, 256>>>(midp, ln_g, ln_b);
    attn_w_kernel<<<dim3(NQ_, H_, B_), 256>>>(qp, kp, midp, wp);
    convout_kernel<<<BQ_ROWS, 256>>>(wp, Wconv, opp);

    // final = outpre @ Wout^T (512 x 768): split-bf16 3-term, split-K=4
    split_kernel<0><<<blks(BQ_ROWS * D_ / 4), T>>>(opp, op2, BQ_ROWS);
    gemm_mma<<<dim3(D_ / 128, BQ_ROWS / 128, 4), T, SMEM>>>(
        op2, Wout2, pp, BQ_ROWS, D_, NKT / 4);
    reduce_k<4><<<blks(BQ_ROWS * D_ / 4), T>>>(pp, out, BQ_ROWS * D_ / 4);
}

// round 11
// speedup vs baseline: 2.2249x; 1.1357x over previous
#include <cuda_runtime.h>
#include <cstdint>

#define B_   8
#define NQ_  64
#define N_   257
#define D_   768
#define H_   6
#define R_   64
#define DH_  128
#define MID_ 4096
#define BN_ROWS 2056
#define BQ_ROWS 512
#define NKT32 (D_ / 32)       // 24 tf32 k-tiles

// fused-GEMM job boundaries (tf32 path)
#define MID_TILES 544          // 17 m-tiles x 32 n-tiles, 24 iters
#define KQ_B0     544          // k: 2 z x 17 x 6 = 204, 12 iters
#define Q_B0      748          // q: 4 z x 4 x 6  = 96,  6 iters
#define TOT_TILES 844

// pre-round segment sizes (float4 units): x | ctx | Wq | Wk | Wv1 | Wout
#define X4    (BQ_ROWS * D_ / 4)        // 98304
#define CTX4  (BN_ROWS * D_ / 4)        // 394752
#define W4    (D_ * D_ / 4)             // 147456
#define WV14  (MID_ * D_ / 4)           // 786432
#define TOT4  (X4 + CTX4 + 3 * W4 + WV14)

// ---------------- scratch (device globals; no allocation allowed) ----------
__device__ __align__(256) float g_rnd[(size_t)TOT4 * 4];   // tf32-rounded inputs
__device__ float g_k[BN_ROWS * (size_t)D_];
__device__ float g_mid[BN_ROWS * (size_t)MID_];
__device__ float g_attn[(size_t)B_ * NQ_ * H_ * N_];       // normalized attn
__device__ float g_w[(size_t)B_ * H_ * NQ_ * R_];
__device__ float g_outpre[BQ_ROWS * (size_t)D_];           // tf32-rounded
// k partials (2 x 2056 x 768) then q partials (4 x 512 x 768); out partials reuse front
__device__ float g_part[2 * BN_ROWS * (size_t)D_ + 4 * BQ_ROWS * (size_t)D_];

// ---------------------------- PTX helpers ----------------------------------
__device__ __forceinline__ unsigned smem_u32(const void* p) {
    return (unsigned)__cvta_generic_to_shared(p);
}
#define CPA16(dst_u32, src_ptr) \
    asm volatile("cp.async.cg.shared.global [%0], [%1], 16;\n" :: "r"(dst_u32), "l"(src_ptr))
#define LDSM_X4(r0, r1, r2, r3, addr) \
    asm volatile("ldmatrix.sync.aligned.m8n8.x4.shared.b16 {%0,%1,%2,%3}, [%4];" \
                 : "=r"(r0), "=r"(r1), "=r"(r2), "=r"(r3) : "r"(addr))
#define MMA1688_TF32(acc, a, b) \
    asm volatile( \
        "mma.sync.aligned.m16n8k8.row.col.f32.tf32.tf32.f32 " \
        "{%0,%1,%2,%3}, {%4,%5,%6,%7}, {%8,%9}, {%0,%1,%2,%3};\n" \
        : "+f"((acc)[0]), "+f"((acc)[1]), "+f"((acc)[2]), "+f"((acc)[3]) \
        : "r"((a)[0]), "r"((a)[1]), "r"((a)[2]), "r"((a)[3]), \
          "r"((b)[0]), "r"((b)[1]))

__device__ __forceinline__ uint32_t sw128(uint32_t off) {
    return off ^ ((off >> 3) & 0x70);
}
__device__ __forceinline__ float rna_tf32(float v) {
    uint32_t t;
    asm("cvt.rna.tf32.f32 %0, %1;" : "=r"(t) : "f"(v));
    return __uint_as_float(t);
}

// ---------------------------------------------------------------------------
// Pre-round all tf32-GEMM inputs to tf32 (RNA) into g_rnd (one flat pass).
// ---------------------------------------------------------------------------
__global__ void round_tf32_kernel(const float* __restrict__ x,
                                  const float* __restrict__ ctx,
                                  const float* __restrict__ Wq,
                                  const float* __restrict__ Wk,
                                  const float* __restrict__ Wv1,
                                  const float* __restrict__ Wout,
                                  float* __restrict__ Y) {
    const int i = blockIdx.x * 256 + threadIdx.x;
    if (i >= TOT4) return;
    int j = i;
    const float4* src;
    if (j < X4)                  src = (const float4*)x;
    else if ((j -= X4) < CTX4)   src = (const float4*)ctx;
    else if ((j -= CTX4) < W4)   src = (const float4*)Wq;
    else if ((j -= W4) < W4)     src = (const float4*)Wk;
    else if ((j -= W4) < WV14)   src = (const float4*)Wv1;
    else { j -= WV14;            src = (const float4*)Wout; }
    float4 v = src[j];
    v.x = rna_tf32(v.x); v.y = rna_tf32(v.y);
    v.z = rna_tf32(v.z); v.w = rna_tf32(v.w);
    ((float4*)Y)[i] = v;
}

// ---------------------------------------------------------------------------
// TF32 GEMM body, 128x128 tile: C = A[M,768] @ B[N,768]^T (A,B pre-rounded).
// BK=32 fp32 (128B rows), 3-stage cp.async, 256 thr = 8 warps (4M x 2N).
// Fragments via ldmatrix.x4 (8x4-tf32 tile == 8x8-b16 tile).
// ---------------------------------------------------------------------------
#define STG_BYTES 32768            // (128 + 128) rows * 128 B

__device__ __forceinline__
void gemm_body_tf32(const float* __restrict__ A,
                    const float* __restrict__ Bm,
                    float* __restrict__ C, int M, int Ncols,
                    int nkt, int kt0, int mt, int nt, char* dyn) {
    const uint32_t base = smem_u32(dyn);

    const int tid = threadIdx.x;
    const int warp = tid >> 5, lane = tid & 31;
    const int wm = warp & 3, wn = warp >> 2;
    const int gr = lane >> 2, tig = lane & 3;
    const int lrow = lane & 7, lmat = lane >> 3;
    const int m0 = mt * 128, n0 = nt * 128;

    float acc[2][8][4];
#pragma unroll
    for (int mi = 0; mi < 2; mi++)
#pragma unroll
        for (int ni = 0; ni < 8; ni++)
#pragma unroll
            for (int j = 0; j < 4; j++) acc[mi][ni][j] = 0.f;

    auto load_stage = [&](int kt) {
        const uint32_t sb = base + (kt % 3) * STG_BYTES;
        const int k0 = (kt0 + kt) * 32;
#pragma unroll
        for (int i = 0; i < 4; i++) {
            const int c = tid + i * 256;
            const int row = c >> 3, c16 = c & 7;
            int grow = m0 + row; if (grow >= M) grow = M - 1;
            CPA16(sb + sw128((uint32_t)(row * 128 + c16 * 16)),
                  A + (size_t)grow * D_ + k0 + c16 * 4);
        }
#pragma unroll
        for (int i = 0; i < 4; i++) {
            const int c = tid + i * 256;
            const int row = c >> 3, c16 = c & 7;
            CPA16(sb + 16384 + sw128((uint32_t)(row * 128 + c16 * 16)),
                  Bm + (size_t)(n0 + row) * D_ + k0 + c16 * 4);
        }
        asm volatile("cp.async.commit_group;\n" ::);
    };

    load_stage(0);
    load_stage(1);

    for (int kt = 0; kt < nkt; kt++) {
        const int s = kt % 3;
        asm volatile("cp.async.wait_group 1;\n" ::);
        __syncthreads();
        if (kt + 2 < nkt) load_stage(kt + 2);
        else asm volatile("cp.async.commit_group;\n" ::);

        const uint32_t sA = base + s * STG_BYTES;
        const uint32_t sB = sA + 16384;
#pragma unroll
        for (int kk = 0; kk < 4; kk++) {
            const int kb = kk * 32;
            uint32_t a[2][4], b[8][2];
#pragma unroll
            for (int mi = 0; mi < 2; mi++) {
                const int r = wm * 32 + mi * 16 + ((lmat & 1) << 3) + lrow;
                LDSM_X4(a[mi][0], a[mi][1], a[mi][2], a[mi][3],
                        sA + sw128((uint32_t)(r * 128 + kb + ((lmat >> 1) << 4))));
            }
#pragma unroll
            for (int gp = 0; gp < 4; gp++) {
                const int n = wn * 64 + gp * 16 + ((lmat >> 1) << 3) + lrow;
                LDSM_X4(b[2 * gp][0], b[2 * gp][1], b[2 * gp + 1][0], b[2 * gp + 1][1],
                        sB + sw128((uint32_t)(n * 128 + kb + ((lmat & 1) << 4))));
            }
#pragma unroll
            for (int mi = 0; mi < 2; mi++)
#pragma unroll
                for (int ni = 0; ni < 8; ni++)
                    MMA1688_TF32(acc[mi][ni], a[mi], b[ni]);
        }
    }

#pragma unroll
    for (int mi = 0; mi < 2; mi++)
#pragma unroll
        for (int ni = 0; ni < 8; ni++) {
            const int c = n0 + wn * 64 + ni * 8 + 2 * tig;
            int r = m0 + wm * 32 + mi * 16 + gr;
            if (r < M) *(float2*)&C[(size_t)r * Ncols + c] =
                make_float2(acc[mi][ni][0], acc[mi][ni][1]);
            r += 8;
            if (r < M) *(float2*)&C[(size_t)r * Ncols + c] =
                make_float2(acc[mi][ni][2], acc[mi][ni][3]);
        }
}

// Fused tf32 launch: mid + k (split-K2) + q (split-K4), one grid.
__global__ __launch_bounds__(256, 2)
void gemm_fused_tf32(const float* __restrict__ ctx,
                     const float* __restrict__ Wv1, float* __restrict__ midp,
                     const float* __restrict__ Wk,  float* __restrict__ kpart,
                     const float* __restrict__ x,
                     const float* __restrict__ Wq,  float* __restrict__ qpart) {
    extern __shared__ char dyn[];
    const int bid = blockIdx.x;
    if (bid < MID_TILES) {
        gemm_body_tf32(ctx, Wv1, midp, BN_ROWS, MID_, NKT32, 0,
                       bid / 32, bid % 32, dyn);
    } else if (bid < Q_B0) {
        const int t = bid - KQ_B0;
        const int z = t / 102, r = t - z * 102;
        gemm_body_tf32(ctx, Wk, kpart + (size_t)z * BN_ROWS * D_, BN_ROWS, D_,
                       NKT32 / 2, z * (NKT32 / 2), r / 6, r % 6, dyn);
    } else {
        const int t = bid - Q_B0;
        const int z = t / 24, r = t - z * 24;
        gemm_body_tf32(x, Wq, qpart + (size_t)z * BQ_ROWS * D_, BQ_ROWS, D_,
                       NKT32 / 4, z * (NKT32 / 4), r / 6, r % 6, dyn);
    }
}

// Out GEMM: outpre(tf32-rounded) @ Wout_r^T, split-K=4 via blockIdx.z.
__global__ __launch_bounds__(256, 2)
void gemm_out_tf32(const float* __restrict__ A, const float* __restrict__ Bm,
                   float* __restrict__ C) {
    extern __shared__ char dyn[];
    gemm_body_tf32(A, Bm, C + (size_t)blockIdx.z * BQ_ROWS * D_, BQ_ROWS, D_,
                   NKT32 / 4, blockIdx.z * (NKT32 / 4), blockIdx.y, blockIdx.x, dyn);
}

// ---------------------------------------------------------------------------
// Split-K reduction: C[i] = sum_{z<KSPL} P[z*elems + i]. float4 vectorized.
// ---------------------------------------------------------------------------
template <int KSPL>
__global__ void reduce_k(const float* __restrict__ P, float* __restrict__ C,
                         int elems4) {
    const int i = blockIdx.x * 256 + threadIdx.x;
    if (i >= elems4) return;
    const float4* p = (const float4*)P;
    float4 v = p[i];
#pragma unroll
    for (int z = 1; z < KSPL; z++) {
        const float4 u = p[(size_t)z * elems4 + i];
        v.x += u.x; v.y += u.y; v.z += u.z; v.w += u.w;
    }
    ((float4*)C)[i] = v;
}

// ---------------------------------------------------------------------------
// Row LayerNorm over MID_=4096, in place, float4-vectorized.
// ---------------------------------------------------------------------------
__global__ void ln_kernel(float* __restrict__ mid,
                          const float* __restrict__ g,
                          const float* __restrict__ bt) {
    const int row = blockIdx.x;
    float4* p = (float4*)(mid + (size_t)row * MID_);
    const float4* g4 = (const float4*)g;
    const float4* b4 = (const float4*)bt;
    const int tid = threadIdx.x;
    const int lane = tid & 31, warp = tid >> 5;

    float4 v[4];
    float s = 0.f, ss = 0.f;
#pragma unroll
    for (int j = 0; j < 4; j++) {
        v[j] = p[tid + (j << 8)];
        s  += v[j].x + v[j].y + v[j].z + v[j].w;
        ss += v[j].x * v[j].x + v[j].y * v[j].y + v[j].z * v[j].z + v[j].w * v[j].w;
    }
#pragma unroll
    for (int off = 16; off; off >>= 1) {
        s  += __shfl_xor_sync(~0u, s,  off);
        ss += __shfl_xor_sync(~0u, ss, off);
    }
    __shared__ float rs[8], rss[8];
    if (lane == 0) { rs[warp] = s; rss[warp] = ss; }
    __syncthreads();
    s = 0.f; ss = 0.f;
#pragma unroll
    for (int k = 0; k < 8; k++) { s += rs[k]; ss += rss[k]; }
    const float mu  = s * (1.f / MID_);
    const float var = ss * (1.f / MID_) - mu * mu;
    const float inv = rsqrtf(var + 1e-5f);
#pragma unroll
    for (int j = 0; j < 4; j++) {
        const int idx = tid + (j << 8);
        const float4 gv = g4[idx], bv = b4[idx];
        float4 o;
        o.x = (v[j].x - mu) * inv * gv.x + bv.x;
        o.y = (v[j].y - mu) * inv * gv.y + bv.y;
        o.z = (v[j].z - mu) * inv * gv.z + bv.z;
        o.w = (v[j].w - mu) * inv * gv.w + bv.w;
        p[idx] = o;
    }
}

// ---------------------------------------------------------------------------
// Attention stage 1: softmax rows. Block per (ig, h, b); 8 i's per block.
// Fuses the q split-K=4 reduction. Writes normalized attn[b,i,h,n].
// ---------------------------------------------------------------------------
__global__ __launch_bounds__(256)
void attn_sim_kernel(const float* __restrict__ qpart,
                     const float* __restrict__ kb,
                     float* __restrict__ attn_g) {
    const int ig = blockIdx.x, h = blockIdx.y, b = blockIdx.z;
    const int i0 = ig * 8;
    const int tid = threadIdx.x, warp = tid >> 5, lane = tid & 31;

    __shared__ float qs[8 * 128];
    __shared__ float sim[8 * 264];

    // q load with fused split-K=4 reduce
    for (int j = tid; j < 1024; j += 256) {
        const int i = j >> 7, d = j & 127;
        const size_t base = (size_t)(b * NQ_ + i0 + i) * D_ + h * DH_ + d;
        float s = 0.f;
#pragma unroll
        for (int z = 0; z < 4; z++) s += qpart[(size_t)z * BQ_ROWS * D_ + base];
        qs[i * 128 + d] = s;
    }
    __syncthreads();

    // sim: warp per n; 8 i-dots per n via float4 lanes + shfl reduce
    for (int n = warp; n < N_; n += 8) {
        const float4 k4 = *(const float4*)(kb + (size_t)(b * N_ + n) * D_ + h * DH_ + lane * 4);
        float acc[8];
#pragma unroll
        for (int i = 0; i < 8; i++) {
            const float4 q4 = *(const float4*)(qs + i * 128 + lane * 4);
            acc[i] = q4.x * k4.x + q4.y * k4.y + q4.z * k4.z + q4.w * k4.w;
        }
#pragma unroll
        for (int i = 0; i < 8; i++)
#pragma unroll
            for (int off = 16; off; off >>= 1)
                acc[i] += __shfl_xor_sync(~0u, acc[i], off);
        if (lane == 0) {
            const float sc = 0.0883883476483184406f;
#pragma unroll
            for (int i = 0; i < 8; i++) sim[i * 264 + n] = acc[i] * sc;
        }
    }
    __syncthreads();

    // softmax: warp w owns row i = w
    {
        const int i = warp;
        float m = -1e30f;
        for (int n = lane; n < N_; n += 32) m = fmaxf(m, sim[i * 264 + n]);
#pragma unroll
        for (int off = 16; off; off >>= 1) m = fmaxf(m, __shfl_xor_sync(~0u, m, off));
        float s = 0.f;
        for (int n = lane; n < N_; n += 32) {
            const float e = __expf(sim[i * 264 + n] - m);
            sim[i * 264 + n] = e;
            s += e;
        }
#pragma unroll
        for (int off = 16; off; off >>= 1) s += __shfl_xor_sync(~0u, s, off);
        const float inv = 1.f / s;
        float* dst = attn_g + ((size_t)(b * NQ_ + i0 + i) * H_ + h) * N_;
        for (int n = lane; n < N_; n += 32) dst[n] = sim[i * 264 + n] * inv;
    }
}

// ---------------------------------------------------------------------------
// Attention stage 2: w[b,h,i,r] = sum_n attn[b,i,h,n] * mid[b,n,i*64+r].
// Block per (i, b); 384 threads = 6h x 64r; mid slice read ONCE for all h.
// ---------------------------------------------------------------------------
__global__ __launch_bounds__(384)
void attn_w2_kernel(const float* __restrict__ attn_g,
                    const float* __restrict__ mid,
                    float* __restrict__ w) {
    const int i = blockIdx.x, b = blockIdx.y;
    const int tid = threadIdx.x;

    __shared__ float ats[H_ * N_];     // 1542 floats
    const float* src = attn_g + (size_t)(b * NQ_ + i) * H_ * N_;
    for (int j = tid; j < H_ * N_; j += 384) ats[j] = src[j];
    __syncthreads();

    const int h = tid / 64, r = tid & 63;
    const float* mp = mid + (size_t)b * N_ * MID_ + i * R_ + r;
    float acc = 0.f;
#pragma unroll 4
    for (int n = 0; n < N_; n++)
        acc += ats[h * N_ + n] * mp[(size_t)n * MID_];
    w[(((size_t)b * H_ + h) * NQ_ + i) * R_ + r] = acc;
}

// ---------------------------------------------------------------------------
// Rank expansion: outpre[b,i,d] = sum_r Wconv[i,d,r] * w[b, d/128, i, r].
// Output stored tf32-rounded (feeds tf32 out-GEMM directly).
// ---------------------------------------------------------------------------
__global__ void convout_kernel(const float* __restrict__ w,
                               const float* __restrict__ Wconv,
                               float* __restrict__ outpre) {
    const int i = blockIdx.x % NQ_;
    const int b = blockIdx.x / NQ_;
    const int tid = threadIdx.x;

    __shared__ float ws[H_ * R_];
    for (int j = tid; j < H_ * R_; j += 256)
        ws[j] = w[(((size_t)b * H_ + (j >> 6)) * NQ_ + i) * R_ + (j & 63)];
    __syncthreads();

    for (int d = tid; d < D_; d += 256) {
        const float* wc = Wconv + ((size_t)i * D_ + d) * R_;
        const float* wv = &ws[(d >> 7) * R_];
        float acc = 0.f;
#pragma unroll
        for (int r = 0; r < R_; r += 4) {
            const float4 c4 = *(const float4*)&wc[r];
            acc += c4.x * wv[r] + c4.y * wv[r + 1] + c4.z * wv[r + 2] + c4.w * wv[r + 3];
        }
        outpre[((size_t)b * NQ_ + i) * D_ + d] = rna_tf32(acc);
    }
}

// ---------------------------------------------------------------------------
extern "C" void kernel_launch(void* const* d_in, const int* in_sizes, int n_in,
                              void* d_out, int out_size) {
    const float* x     = (const float*)d_in[0];
    const float* ctx   = (const float*)d_in[1];
    const float* Wq    = (const float*)d_in[2];
    const float* Wk    = (const float*)d_in[3];
    const float* Wv1   = (const float*)d_in[4];
    const float* ln_g  = (const float*)d_in[5];
    const float* ln_b  = (const float*)d_in[6];
    const float* Wconv = (const float*)d_in[7];
    const float* Wout  = (const float*)d_in[8];
    float* out = (float*)d_out;

    float *kp, *midp, *attn, *wp, *opp, *pp, *rnd;
    cudaGetSymbolAddress((void**)&kp,   g_k);
    cudaGetSymbolAddress((void**)&midp, g_mid);
    cudaGetSymbolAddress((void**)&attn, g_attn);
    cudaGetSymbolAddress((void**)&wp,   g_w);
    cudaGetSymbolAddress((void**)&opp,  g_outpre);
    cudaGetSymbolAddress((void**)&pp,   g_part);
    cudaGetSymbolAddress((void**)&rnd,  g_rnd);
    float* kpart = pp;
    float* qpart = pp + 2 * (size_t)BN_ROWS * D_;
    float* x_r    = rnd;
    float* ctx_r  = x_r + (size_t)X4 * 4;
    float* Wq_r   = ctx_r + (size_t)CTX4 * 4;
    float* Wk_r   = Wq_r + (size_t)W4 * 4;
    float* Wv1_r  = Wk_r + (size_t)W4 * 4;
    float* Wout_r = Wv1_r + (size_t)WV14 * 4;

    const int SMEM = 3 * STG_BYTES;   // 98304
    cudaFuncSetAttribute(gemm_fused_tf32, cudaFuncAttributeMaxDynamicSharedMemorySize, SMEM);
    cudaFuncSetAttribute(gemm_out_tf32,   cudaFuncAttributeMaxDynamicSharedMemorySize, SMEM);

    const int T = 256;
    auto blks = [](int n) { return (n + 255) / 256; };

    // pre-round all tf32-GEMM inputs (RNA), now including Wout
    round_tf32_kernel<<<blks(TOT4), T>>>(x, ctx, Wq, Wk, Wv1, Wout, rnd);

    // ONE tf32 launch: mid + k(split2) + q(split4), 844 CTAs
    gemm_fused_tf32<<<TOT_TILES, T, SMEM>>>(ctx_r, Wv1_r, midp, Wk_r, kpart,
                                            x_r, Wq_r, qpart);
    reduce_k<2><<<blks(BN_ROWS * D_ / 4), T>>>(kpart, kp, BN_ROWS * D_ / 4);

    ln_kernel<<<BN_ROWS, 256>>>(midp, ln_g, ln_b);

    // attention: softmax (q-reduce fused) then h-shared rank contraction
    attn_sim_kernel<<<dim3(NQ_ / 8, H_, B_), 256>>>(qpart, kp, attn);
    attn_w2_kernel<<<dim3(NQ_, B_), 384>>>(attn, midp, wp);

    convout_kernel<<<BQ_ROWS, 256>>>(wp, Wconv, opp);

    // final = outpre @ Wout^T, tf32, split-K=4 (partials reuse g_part front)
    gemm_out_tf32<<<dim3(D_ / 128, BQ_ROWS / 128, 4), T, SMEM>>>(opp, Wout_r, pp);
    reduce_k<4><<<blks(BQ_ROWS * D_ / 4), T>>>(pp, out, BQ_ROWS * D_ / 4);
}

// round 12
// speedup vs baseline: 2.2327x; 1.0035x over previous
#include <cuda_runtime.h>
#include <cstdint>

#define B_   8
#define NQ_  64
#define N_   257
#define D_   768
#define H_   6
#define R_   64
#define DH_  128
#define MID_ 4096
#define BN_ROWS 2056
#define BQ_ROWS 512
#define NKT32 (D_ / 32)       // 24 tf32 k-tiles

// fused-GEMM job boundaries (no split-K; all 24-iter CTAs)
#define MID_TILES 544          // 17 m-tiles x 32 n-tiles
#define K_B0      544          // k: 17 x 6 = 102
#define Q_B0      646          // q: 4 x 6 = 24
#define TOT_TILES 670

// pre-round segment sizes (float4 units): x | ctx | Wq | Wk | Wv1 | Wout
#define X4    (BQ_ROWS * D_ / 4)
#define CTX4  (BN_ROWS * D_ / 4)
#define W4    (D_ * D_ / 4)
#define WV14  (MID_ * D_ / 4)
#define TOT4  (X4 + CTX4 + 3 * W4 + WV14)

// ---------------- scratch (device globals; no allocation allowed) ----------
__device__ __align__(256) float g_rnd[(size_t)TOT4 * 4];   // tf32-rounded inputs
__device__ float g_q[BQ_ROWS * (size_t)D_];
__device__ float g_k[BN_ROWS * (size_t)D_];
__device__ float g_mid[BN_ROWS * (size_t)MID_];            // raw (pre-LN)
__device__ float g_stats[BN_ROWS * 2];                     // mu, inv per row
__device__ float g_attn[(size_t)B_ * NQ_ * H_ * N_];       // normalized attn
__device__ float g_w[(size_t)B_ * H_ * NQ_ * R_];
__device__ float g_outpre[BQ_ROWS * (size_t)D_];           // tf32-rounded
__device__ float g_part[4 * BQ_ROWS * (size_t)D_];         // out-GEMM partials

// ---------------------------- PTX helpers ----------------------------------
__device__ __forceinline__ unsigned smem_u32(const void* p) {
    return (unsigned)__cvta_generic_to_shared(p);
}
#define CPA16(dst_u32, src_ptr) \
    asm volatile("cp.async.cg.shared.global [%0], [%1], 16;\n" :: "r"(dst_u32), "l"(src_ptr))
#define LDSM_X4(r0, r1, r2, r3, addr) \
    asm volatile("ldmatrix.sync.aligned.m8n8.x4.shared.b16 {%0,%1,%2,%3}, [%4];" \
                 : "=r"(r0), "=r"(r1), "=r"(r2), "=r"(r3) : "r"(addr))
#define MMA1688_TF32(acc, a, b) \
    asm volatile( \
        "mma.sync.aligned.m16n8k8.row.col.f32.tf32.tf32.f32 " \
        "{%0,%1,%2,%3}, {%4,%5,%6,%7}, {%8,%9}, {%0,%1,%2,%3};\n" \
        : "+f"((acc)[0]), "+f"((acc)[1]), "+f"((acc)[2]), "+f"((acc)[3]) \
        : "r"((a)[0]), "r"((a)[1]), "r"((a)[2]), "r"((a)[3]), \
          "r"((b)[0]), "r"((b)[1]))

__device__ __forceinline__ uint32_t sw128(uint32_t off) {
    return off ^ ((off >> 3) & 0x70);
}
__device__ __forceinline__ float rna_tf32(float v) {
    uint32_t t;
    asm("cvt.rna.tf32.f32 %0, %1;" : "=r"(t) : "f"(v));
    return __uint_as_float(t);
}

// ---------------------------------------------------------------------------
// Pre-round all tf32-GEMM inputs to tf32 (RNA) into g_rnd (one flat pass).
// ---------------------------------------------------------------------------
__global__ void round_tf32_kernel(const float* __restrict__ x,
                                  const float* __restrict__ ctx,
                                  const float* __restrict__ Wq,
                                  const float* __restrict__ Wk,
                                  const float* __restrict__ Wv1,
                                  const float* __restrict__ Wout,
                                  float* __restrict__ Y) {
    const int i = blockIdx.x * 256 + threadIdx.x;
    if (i >= TOT4) return;
    int j = i;
    const float4* src;
    if (j < X4)                  src = (const float4*)x;
    else if ((j -= X4) < CTX4)   src = (const float4*)ctx;
    else if ((j -= CTX4) < W4)   src = (const float4*)Wq;
    else if ((j -= W4) < W4)     src = (const float4*)Wk;
    else if ((j -= W4) < WV14)   src = (const float4*)Wv1;
    else { j -= WV14;            src = (const float4*)Wout; }
    float4 v = src[j];
    v.x = rna_tf32(v.x); v.y = rna_tf32(v.y);
    v.z = rna_tf32(v.z); v.w = rna_tf32(v.w);
    ((float4*)Y)[i] = v;
}

// ---------------------------------------------------------------------------
// TF32 GEMM body, 128x128 tile (as R10/R11 — proven).
// ---------------------------------------------------------------------------
#define STG_BYTES 32768

__device__ __forceinline__
void gemm_body_tf32(const float* __restrict__ A,
                    const float* __restrict__ Bm,
                    float* __restrict__ C, int M, int Ncols,
                    int nkt, int kt0, int mt, int nt, char* dyn) {
    const uint32_t base = smem_u32(dyn);

    const int tid = threadIdx.x;
    const int warp = tid >> 5, lane = tid & 31;
    const int wm = warp & 3, wn = warp >> 2;
    const int gr = lane >> 2, tig = lane & 3;
    const int lrow = lane & 7, lmat = lane >> 3;
    const int m0 = mt * 128, n0 = nt * 128;

    float acc[2][8][4];
#pragma unroll
    for (int mi = 0; mi < 2; mi++)
#pragma unroll
        for (int ni = 0; ni < 8; ni++)
#pragma unroll
            for (int j = 0; j < 4; j++) acc[mi][ni][j] = 0.f;

    auto load_stage = [&](int kt) {
        const uint32_t sb = base + (kt % 3) * STG_BYTES;
        const int k0 = (kt0 + kt) * 32;
#pragma unroll
        for (int i = 0; i < 4; i++) {
            const int c = tid + i * 256;
            const int row = c >> 3, c16 = c & 7;
            int grow = m0 + row; if (grow >= M) grow = M - 1;
            CPA16(sb + sw128((uint32_t)(row * 128 + c16 * 16)),
                  A + (size_t)grow * D_ + k0 + c16 * 4);
        }
#pragma unroll
        for (int i = 0; i < 4; i++) {
            const int c = tid + i * 256;
            const int row = c >> 3, c16 = c & 7;
            CPA16(sb + 16384 + sw128((uint32_t)(row * 128 + c16 * 16)),
                  Bm + (size_t)(n0 + row) * D_ + k0 + c16 * 4);
        }
        asm volatile("cp.async.commit_group;\n" ::);
    };

    load_stage(0);
    load_stage(1);

    for (int kt = 0; kt < nkt; kt++) {
        const int s = kt % 3;
        asm volatile("cp.async.wait_group 1;\n" ::);
        __syncthreads();
        if (kt + 2 < nkt) load_stage(kt + 2);
        else asm volatile("cp.async.commit_group;\n" ::);

        const uint32_t sA = base + s * STG_BYTES;
        const uint32_t sB = sA + 16384;
#pragma unroll
        for (int kk = 0; kk < 4; kk++) {
            const int kb = kk * 32;
            uint32_t a[2][4], b[8][2];
#pragma unroll
            for (int mi = 0; mi < 2; mi++) {
                const int r = wm * 32 + mi * 16 + ((lmat & 1) << 3) + lrow;
                LDSM_X4(a[mi][0], a[mi][1], a[mi][2], a[mi][3],
                        sA + sw128((uint32_t)(r * 128 + kb + ((lmat >> 1) << 4))));
            }
#pragma unroll
            for (int gp = 0; gp < 4; gp++) {
                const int n = wn * 64 + gp * 16 + ((lmat >> 1) << 3) + lrow;
                LDSM_X4(b[2 * gp][0], b[2 * gp][1], b[2 * gp + 1][0], b[2 * gp + 1][1],
                        sB + sw128((uint32_t)(n * 128 + kb + ((lmat & 1) << 4))));
            }
#pragma unroll
            for (int mi = 0; mi < 2; mi++)
#pragma unroll
                for (int ni = 0; ni < 8; ni++)
                    MMA1688_TF32(acc[mi][ni], a[mi], b[ni]);
        }
    }

#pragma unroll
    for (int mi = 0; mi < 2; mi++)
#pragma unroll
        for (int ni = 0; ni < 8; ni++) {
            const int c = n0 + wn * 64 + ni * 8 + 2 * tig;
            int r = m0 + wm * 32 + mi * 16 + gr;
            if (r < M) *(float2*)&C[(size_t)r * Ncols + c] =
                make_float2(acc[mi][ni][0], acc[mi][ni][1]);
            r += 8;
            if (r < M) *(float2*)&C[(size_t)r * Ncols + c] =
                make_float2(acc[mi][ni][2], acc[mi][ni][3]);
        }
}

// Fused tf32 launch: mid + k + q, one grid, no split-K (direct writes).
__global__ __launch_bounds__(256, 2)
void gemm_fused_tf32(const float* __restrict__ ctx,
                     const float* __restrict__ Wv1, float* __restrict__ midp,
                     const float* __restrict__ Wk,  float* __restrict__ kp,
                     const float* __restrict__ x,
                     const float* __restrict__ Wq,  float* __restrict__ qp) {
    extern __shared__ char dyn[];
    const int bid = blockIdx.x;
    if (bid < MID_TILES) {
        gemm_body_tf32(ctx, Wv1, midp, BN_ROWS, MID_, NKT32, 0,
                       bid / 32, bid % 32, dyn);
    } else if (bid < Q_B0) {
        const int t = bid - K_B0;
        gemm_body_tf32(ctx, Wk, kp, BN_ROWS, D_, NKT32, 0, t / 6, t % 6, dyn);
    } else {
        const int t = bid - Q_B0;
        gemm_body_tf32(x, Wq, qp, BQ_ROWS, D_, NKT32, 0, t / 6, t % 6, dyn);
    }
}

// Out GEMM: outpre(tf32-rounded) @ Wout_r^T, split-K=4 via blockIdx.z.
__global__ __launch_bounds__(256, 2)
void gemm_out_tf32(const float* __restrict__ A, const float* __restrict__ Bm,
                   float* __restrict__ C) {
    extern __shared__ char dyn[];
    gemm_body_tf32(A, Bm, C + (size_t)blockIdx.z * BQ_ROWS * D_, BQ_ROWS, D_,
                   NKT32 / 4, blockIdx.z * (NKT32 / 4), blockIdx.y, blockIdx.x, dyn);
}

// ---------------------------------------------------------------------------
// Split-K reduction (out-GEMM only).
// ---------------------------------------------------------------------------
template <int KSPL>
__global__ void reduce_k(const float* __restrict__ P, float* __restrict__ C,
                         int elems4) {
    const int i = blockIdx.x * 256 + threadIdx.x;
    if (i >= elems4) return;
    const float4* p = (const float4*)P;
    float4 v = p[i];
#pragma unroll
    for (int z = 1; z < KSPL; z++) {
        const float4 u = p[(size_t)z * elems4 + i];
        v.x += u.x; v.y += u.y; v.z += u.z; v.w += u.w;
    }
    ((float4*)C)[i] = v;
}

// ---------------------------------------------------------------------------
// LN stats only: mu, inv per row of mid (read-only pass; application deferred
// into attn_w2). One block (256 thr) per row.
// ---------------------------------------------------------------------------
__global__ void ln_stats_kernel(const float* __restrict__ mid,
                                float* __restrict__ stats) {
    const int row = blockIdx.x;
    const float4* p = (const float4*)(mid + (size_t)row * MID_);
    const int tid = threadIdx.x;
    const int lane = tid & 31, warp = tid >> 5;

    float s = 0.f, ss = 0.f;
#pragma unroll
    for (int j = 0; j < 4; j++) {
        const float4 v = p[tid + (j << 8)];
        s  += v.x + v.y + v.z + v.w;
        ss += v.x * v.x + v.y * v.y + v.z * v.z + v.w * v.w;
    }
#pragma unroll
    for (int off = 16; off; off >>= 1) {
        s  += __shfl_xor_sync(~0u, s,  off);
        ss += __shfl_xor_sync(~0u, ss, off);
    }
    __shared__ float rs[8], rss[8];
    if (lane == 0) { rs[warp] = s; rss[warp] = ss; }
    __syncthreads();
    if (tid == 0) {
        s = 0.f; ss = 0.f;
#pragma unroll
        for (int k = 0; k < 8; k++) { s += rs[k]; ss += rss[k]; }
        const float mu  = s * (1.f / MID_);
        const float var = ss * (1.f / MID_) - mu * mu;
        stats[row * 2]     = mu;
        stats[row * 2 + 1] = rsqrtf(var + 1e-5f);
    }
}

// ---------------------------------------------------------------------------
// Attention stage 1: softmax rows. Block per (ig, h, b); 8 i's per block.
// Writes normalized attn[b,i,h,n].
// ---------------------------------------------------------------------------
__global__ __launch_bounds__(256)
void attn_sim_kernel(const float* __restrict__ qb,
                     const float* __restrict__ kb,
                     float* __restrict__ attn_g) {
    const int ig = blockIdx.x, h = blockIdx.y, b = blockIdx.z;
    const int i0 = ig * 8;
    const int tid = threadIdx.x, warp = tid >> 5, lane = tid & 31;

    __shared__ float qs[8 * 128];
    __shared__ float sim[8 * 264];

    for (int j = tid; j < 1024; j += 256) {
        const int i = j >> 7, d = j & 127;
        qs[i * 128 + d] = qb[(size_t)(b * NQ_ + i0 + i) * D_ + h * DH_ + d];
    }
    __syncthreads();

    for (int n = warp; n < N_; n += 8) {
        const float4 k4 = *(const float4*)(kb + (size_t)(b * N_ + n) * D_ + h * DH_ + lane * 4);
        float acc[8];
#pragma unroll
        for (int i = 0; i < 8; i++) {
            const float4 q4 = *(const float4*)(qs + i * 128 + lane * 4);
            acc[i] = q4.x * k4.x + q4.y * k4.y + q4.z * k4.z + q4.w * k4.w;
        }
#pragma unroll
        for (int i = 0; i < 8; i++)
#pragma unroll
            for (int off = 16; off; off >>= 1)
                acc[i] += __shfl_xor_sync(~0u, acc[i], off);
        if (lane == 0) {
            const float sc = 0.0883883476483184406f;
#pragma unroll
            for (int i = 0; i < 8; i++) sim[i * 264 + n] = acc[i] * sc;
        }
    }
    __syncthreads();

    {
        const int i = warp;
        float m = -1e30f;
        for (int n = lane; n < N_; n += 32) m = fmaxf(m, sim[i * 264 + n]);
#pragma unroll
        for (int off = 16; off; off >>= 1) m = fmaxf(m, __shfl_xor_sync(~0u, m, off));
        float s = 0.f;
        for (int n = lane; n < N_; n += 32) {
            const float e = __expf(sim[i * 264 + n] - m);
            sim[i * 264 + n] = e;
            s += e;
        }
#pragma unroll
        for (int off = 16; off; off >>= 1) s += __shfl_xor_sync(~0u, s, off);
        const float inv = 1.f / s;
        float* dst = attn_g + ((size_t)(b * NQ_ + i0 + i) * H_ + h) * N_;
        for (int n = lane; n < N_; n += 32) dst[n] = sim[i * 264 + n] * inv;
    }
}

// ---------------------------------------------------------------------------
// Attention stage 2 with inline LayerNorm (algebraic form, Σa=1):
//   a'[h,n] = a[h,n]·inv[n];  S2[h] = Σ a'·mu
//   w[h,r]  = g[c]·(Σ a'[h,n]·mid_raw[n,c] − S2[h]) + bt[c],  c = i·64+r
// Block per (i, b); 384 threads = 6h x 64r; mid slice read ONCE for all h.
// ---------------------------------------------------------------------------
__global__ __launch_bounds__(384)
void attn_w2_kernel(const float* __restrict__ attn_g,
                    const float* __restrict__ mid,
                    const float* __restrict__ stats,
                    const float* __restrict__ ln_g,
                    const float* __restrict__ ln_b,
                    float* __restrict__ w) {
    const int i = blockIdx.x, b = blockIdx.y;
    const int tid = threadIdx.x;
    const int h = tid / 64, r = tid & 63;

    __shared__ float ats[H_ * N_];     // a' = a * inv
    __shared__ float muv[N_];
    __shared__ float s2p[H_][64];
    __shared__ float s2[H_];

    // load per-row stats for this batch
    for (int n = tid; n < N_; n += 384) {
        muv[n] = stats[(b * N_ + n) * 2];
    }
    __syncthreads();   // muv ready before a' uses inv... (inv loaded below per element)

    const float* src = attn_g + (size_t)(b * NQ_ + i) * H_ * N_;
    for (int j = tid; j < H_ * N_; j += 384) {
        const int n = j % N_;
        ats[j] = src[j] * stats[(b * N_ + n) * 2 + 1];
    }
    __syncthreads();

    // S2[h] = sum_n a'[h,n] * mu[n]
    {
        float p = 0.f;
        for (int n = r; n < N_; n += 64) p += ats[h * N_ + n] * muv[n];
        s2p[h][r] = p;
    }
    __syncthreads();
    if (r == 0) {
        float t = 0.f;
#pragma unroll
        for (int j = 0; j < 64; j++) t += s2p[h][j];
        s2[h] = t;
    }
    __syncthreads();

    const int c = i * R_ + r;
    const float* mp = mid + (size_t)b * N_ * MID_ + c;
    float acc = 0.f;
#pragma unroll 4
    for (int n = 0; n < N_; n++)
        acc += ats[h * N_ + n] * mp[(size_t)n * MID_];
    w[(((size_t)b * H_ + h) * NQ_ + i) * R_ + r] =
        ln_g[c] * (acc - s2[h]) + ln_b[c];
}

// ---------------------------------------------------------------------------
// Rank expansion: outpre[b,i,d] = sum_r Wconv[i,d,r] * w[b, d/128, i, r].
// Output stored tf32-rounded (feeds tf32 out-GEMM directly).
// ---------------------------------------------------------------------------
__global__ void convout_kernel(const float* __restrict__ w,
                               const float* __restrict__ Wconv,
                               float* __restrict__ outpre) {
    const int i = blockIdx.x % NQ_;
    const int b = blockIdx.x / NQ_;
    const int tid = threadIdx.x;

    __shared__ float ws[H_ * R_];
    for (int j = tid; j < H_ * R_; j += 256)
        ws[j] = w[(((size_t)b * H_ + (j >> 6)) * NQ_ + i) * R_ + (j & 63)];
    __syncthreads();

    for (int d = tid; d < D_; d += 256) {
        const float* wc = Wconv + ((size_t)i * D_ + d) * R_;
        const float* wv = &ws[(d >> 7) * R_];
        float acc = 0.f;
#pragma unroll
        for (int r = 0; r < R_; r += 4) {
            const float4 c4 = *(const float4*)&wc[r];
            acc += c4.x * wv[r] + c4.y * wv[r + 1] + c4.z * wv[r + 2] + c4.w * wv[r + 3];
        }
        outpre[((size_t)b * NQ_ + i) * D_ + d] = rna_tf32(acc);
    }
}

// ---------------------------------------------------------------------------
extern "C" void kernel_launch(void* const* d_in, const int* in_sizes, int n_in,
                              void* d_out, int out_size) {
    const float* x     = (const float*)d_in[0];
    const float* ctx   = (const float*)d_in[1];
    const float* Wq    = (const float*)d_in[2];
    const float* Wk    = (const float*)d_in[3];
    const float* Wv1   = (const float*)d_in[4];
    const float* ln_g  = (const float*)d_in[5];
    const float* ln_b  = (const float*)d_in[6];
    const float* Wconv = (const float*)d_in[7];
    const float* Wout  = (const float*)d_in[8];
    float* out = (float*)d_out;

    float *qp, *kp, *midp, *st, *attn, *wp, *opp, *pp, *rnd;
    cudaGetSymbolAddress((void**)&qp,   g_q);
    cudaGetSymbolAddress((void**)&kp,   g_k);
    cudaGetSymbolAddress((void**)&midp, g_mid);
    cudaGetSymbolAddress((void**)&st,   g_stats);
    cudaGetSymbolAddress((void**)&attn, g_attn);
    cudaGetSymbolAddress((void**)&wp,   g_w);
    cudaGetSymbolAddress((void**)&opp,  g_outpre);
    cudaGetSymbolAddress((void**)&pp,   g_part);
    cudaGetSymbolAddress((void**)&rnd,  g_rnd);
    float* x_r    = rnd;
    float* ctx_r  = x_r + (size_t)X4 * 4;
    float* Wq_r   = ctx_r + (size_t)CTX4 * 4;
    float* Wk_r   = Wq_r + (size_t)W4 * 4;
    float* Wv1_r  = Wk_r + (size_t)W4 * 4;
    float* Wout_r = Wv1_r + (size_t)WV14 * 4;

    const int SMEM = 3 * STG_BYTES;   // 98304
    cudaFuncSetAttribute(gemm_fused_tf32, cudaFuncAttributeMaxDynamicSharedMemorySize, SMEM);
    cudaFuncSetAttribute(gemm_out_tf32,   cudaFuncAttributeMaxDynamicSharedMemorySize, SMEM);

    const int T = 256;
    auto blks = [](int n) { return (n + 255) / 256; };

    // pre-round all tf32-GEMM inputs (RNA)
    round_tf32_kernel<<<blks(TOT4), T>>>(x, ctx, Wq, Wk, Wv1, Wout, rnd);

    // ONE tf32 launch: mid + k + q (direct writes, no split-K)
    gemm_fused_tf32<<<TOT_TILES, T, SMEM>>>(ctx_r, Wv1_r, midp, Wk_r, kp,
                                            x_r, Wq_r, qp);

    // LN stats (application deferred into attn_w2)
    ln_stats_kernel<<<BN_ROWS, 256>>>(midp, st);

    // attention: softmax, then h-shared rank contraction with inline LN
    attn_sim_kernel<<<dim3(NQ_ / 8, H_, B_), 256>>>(qp, kp, attn);
    attn_w2_kernel<<<dim3(NQ_, B_), 384>>>(attn, midp, st, ln_g, ln_b, wp);

    convout_kernel<<<BQ_ROWS, 256>>>(wp, Wconv, opp);

    // final = outpre @ Wout^T, tf32, split-K=4
    gemm_out_tf32<<<dim3(D_ / 128, BQ_ROWS / 128, 4), T, SMEM>>>(opp, Wout_r, pp);
    reduce_k<4><<<blks(BQ_ROWS * D_ / 4), T>>>(pp, out, BQ_ROWS * D_ / 4);
}